// round 11
// baseline (speedup 1.0000x reference)
#include <cuda_runtime.h>
#include <cuda_fp16.h>
#include <math.h>
#include <stdint.h>

// ---------------------------------------------------------------------------
// Problem constants
// ---------------------------------------------------------------------------
#define BATCH   2
#define SLEN    2048
#define EMB     2048
#define NHEAD   16
#define QRANK   1536
#define KVRANK  512
#define QK_D    128
#define V_D     128
#define MROWS   (BATCH * SLEN)        // 4096
#define BHN     (BATCH * NHEAD)       // 32
#define NXC     (QRANK + 576)         // 2112

// ------------------------- fp32 scratch -----------------------------------
__device__ float  g_XC [(size_t)MROWS * NXC];           // only cols >=2048 written/read
__device__ float  g_Q  [(size_t)MROWS * (NHEAD * QK_D)];
__device__ float  g_KVB[(size_t)MROWS * 3072];
__device__ float2 g_rope[SLEN * 32];                    // (cos, sin)

// ------------------------- fp16 buffers -----------------------------------
__device__ __half g_x_hi   [(size_t)MROWS * EMB];
__device__ __half g_x_lo   [(size_t)MROWS * EMB];
__device__ __half g_qakva_h[(size_t)NXC * EMB];
__device__ __half g_qb_h   [(size_t)(NHEAD * QK_D) * QRANK];
__device__ __half g_kvb_h  [(size_t)3072 * KVRANK];
__device__ __half g_ow_h   [(size_t)EMB * (NHEAD * V_D)];
__device__ __half g_XC_hi  [(size_t)MROWS * NXC];
__device__ __half g_XC_lo  [(size_t)MROWS * NXC];
__device__ __half g_Qb_hi  [(size_t)BHN * SLEN * QK_D];
__device__ __half g_Qb_lo  [(size_t)BHN * SLEN * QK_D];
__device__ __half g_Kb_h   [(size_t)BHN * SLEN * QK_D];
__device__ __half g_Vt_h   [(size_t)BHN * V_D * SLEN];
__device__ __half g_O_hi   [(size_t)MROWS * (NHEAD * V_D)];
__device__ __half g_O_lo   [(size_t)MROWS * (NHEAD * V_D)];

// ---------------------------------------------------------------------------
// PTX helpers
// ---------------------------------------------------------------------------
__device__ __forceinline__ uint32_t cvta_s(const void* p) {
    return (uint32_t)__cvta_generic_to_shared(p);
}
__device__ __forceinline__ void cp16(uint32_t dst, const void* src) {
    asm volatile("cp.async.cg.shared.global [%0], [%1], 16;"
                 :: "r"(dst), "l"(src) : "memory");
}
__device__ __forceinline__ void cp16_pred(uint32_t dst, const void* src, bool valid) {
    const int sz = valid ? 16 : 0;
    asm volatile("cp.async.cg.shared.global [%0], [%1], 16, %2;"
                 :: "r"(dst), "l"(src), "r"(sz) : "memory");
}
__device__ __forceinline__ void cp_commit() {
    asm volatile("cp.async.commit_group;" ::: "memory");
}
__device__ __forceinline__ void ldm_x4(uint32_t* r, uint32_t addr) {
    asm volatile("ldmatrix.sync.aligned.m8n8.x4.shared.b16 {%0,%1,%2,%3}, [%4];"
                 : "=r"(r[0]), "=r"(r[1]), "=r"(r[2]), "=r"(r[3]) : "r"(addr));
}
__device__ __forceinline__ void ldm_x2(uint32_t& r0, uint32_t& r1, uint32_t addr) {
    asm volatile("ldmatrix.sync.aligned.m8n8.x2.shared.b16 {%0,%1}, [%2];"
                 : "=r"(r0), "=r"(r1) : "r"(addr));
}
__device__ __forceinline__ void mma_f16(float* c, const uint32_t* a,
                                        const uint32_t* b) {
    asm volatile(
        "mma.sync.aligned.m16n8k16.row.col.f32.f16.f16.f32 "
        "{%0,%1,%2,%3}, {%4,%5,%6,%7}, {%8,%9}, {%0,%1,%2,%3};"
        : "+f"(c[0]), "+f"(c[1]), "+f"(c[2]), "+f"(c[3])
        : "r"(a[0]), "r"(a[1]), "r"(a[2]), "r"(a[3]), "r"(b[0]), "r"(b[1]));
}
__device__ __forceinline__ uint32_t pack_h2(float lo, float hi) {
    uint32_t r;
    asm("cvt.rn.f16x2.f32 %0, %1, %2;" : "=r"(r) : "f"(hi), "f"(lo));
    return r;
}
__device__ __forceinline__ float h_res(float v) {
    return v - __half2float(__float2half_rn(v));
}

// ---------------------------------------------------------------------------
// HMMA 2-term fp16 GEMM (NT) — identical to R10
// ---------------------------------------------------------------------------
#define LDP 40
#define TILE_B (128 * LDP * 2)
#define STAGE_B (3 * TILE_B)
#define GEMM_SMEM (2 * STAGE_B)

__device__ __forceinline__ void gload_stage(
    uint32_t sb, const __half* Ahi, const __half* Alo, int lda,
    const __half* Bh, int bm, int bn, int k0, int K, int N, int tid)
{
    #pragma unroll
    for (int idx = tid; idx < 512; idx += 256) {
        const int r = idx >> 2, c = idx & 3;
        const uint32_t so = (uint32_t)(r * LDP * 2 + c * 16);
        const size_t ga = (size_t)(bm + r) * lda + k0 + c * 8;
        cp16(sb + 0 * TILE_B + so, Ahi + ga);
        cp16(sb + 1 * TILE_B + so, Alo + ga);
        const bool v = (bn + r) < N;
        const size_t gb = v ? ((size_t)(bn + r) * K + k0 + c * 8) : 0;
        cp16_pred(sb + 2 * TILE_B + so, Bh + gb, v);
    }
}

__device__ __forceinline__ void gemm_body(
    uint32_t sbase,
    const __half* __restrict__ Ahi, const __half* __restrict__ Alo, int lda,
    const __half* __restrict__ Bh,
    float* __restrict__ C, __half* __restrict__ Chi, __half* __restrict__ Clo,
    int N, int K, int ldc, int bm, int bn, int c0)
{
    const int tid  = threadIdx.x;
    const int wid  = tid >> 5;
    const int lane = tid & 31;
    const int warp_m = (wid >> 2) * 64;
    const int warp_n = (wid & 3) * 32;
    const int nk = K / 32;

    float acc[4][4][4];
    #pragma unroll
    for (int i = 0; i < 4; ++i)
        #pragma unroll
        for (int j = 0; j < 4; ++j)
            #pragma unroll
            for (int q = 0; q < 4; ++q) acc[i][j][q] = 0.f;

    gload_stage(sbase, Ahi, Alo, lda, Bh, bm, bn, 0, K, N, tid);
    cp_commit();

    const int a_row = lane & 15;
    const int a_coff = (lane >> 4) << 3;
    const int b_row = lane & 7;
    const int b_coff = ((lane >> 3) & 1) << 3;

    for (int i = 0; i < nk; ++i) {
        if (i + 1 < nk) {
            gload_stage(sbase + ((i + 1) & 1) * STAGE_B, Ahi, Alo, lda, Bh,
                        bm, bn, (i + 1) * 32, K, N, tid);
            cp_commit();
            asm volatile("cp.async.wait_group 1;" ::: "memory");
        } else {
            asm volatile("cp.async.wait_group 0;" ::: "memory");
        }
        __syncthreads();

        const uint32_t sb = sbase + (i & 1) * STAGE_B;
        #pragma unroll
        for (int kc = 0; kc < 2; ++kc) {
            const int kel = kc * 16;
            uint32_t ah[4][4], al[4][4];
            #pragma unroll
            for (int mi = 0; mi < 4; ++mi) {
                const uint32_t ao = (uint32_t)((warp_m + mi * 16 + a_row) * LDP
                                               + kel + a_coff) * 2;
                ldm_x4(ah[mi], sb + ao);
                ldm_x4(al[mi], sb + TILE_B + ao);
            }
            #pragma unroll
            for (int ni = 0; ni < 4; ++ni) {
                const uint32_t bo = (uint32_t)((warp_n + ni * 8 + b_row) * LDP
                                               + kel + b_coff) * 2;
                uint32_t bh[2];
                ldm_x2(bh[0], bh[1], sb + 2 * TILE_B + bo);
                #pragma unroll
                for (int mi = 0; mi < 4; ++mi) {
                    mma_f16(acc[mi][ni], ah[mi], bh);
                    mma_f16(acc[mi][ni], al[mi], bh);
                }
            }
        }
        __syncthreads();
    }

    const int er = lane >> 2;
    const int ec = (lane & 3) * 2;
    #pragma unroll
    for (int mi = 0; mi < 4; ++mi) {
        #pragma unroll
        for (int ni = 0; ni < 4; ++ni) {
            const int col = bn + warp_n + ni * 8 + ec;
            if (col < N) {
                const int r0 = bm + warp_m + mi * 16 + er;
                const float a0 = acc[mi][ni][0], a1 = acc[mi][ni][1];
                const float a2 = acc[mi][ni][2], a3 = acc[mi][ni][3];
                if (C && col >= c0) {
                    *(float2*)(C + (size_t)r0 * ldc + col) = make_float2(a0, a1);
                    *(float2*)(C + (size_t)(r0 + 8) * ldc + col) = make_float2(a2, a3);
                }
                if (Chi) {
                    *(uint32_t*)(Chi + (size_t)r0 * ldc + col) = pack_h2(a0, a1);
                    *(uint32_t*)(Clo + (size_t)r0 * ldc + col) =
                        pack_h2(h_res(a0), h_res(a1));
                    *(uint32_t*)(Chi + (size_t)(r0 + 8) * ldc + col) = pack_h2(a2, a3);
                    *(uint32_t*)(Clo + (size_t)(r0 + 8) * ldc + col) =
                        pack_h2(h_res(a2), h_res(a3));
                }
            }
        }
    }
}

__global__ __launch_bounds__(256, 2)
void gemm_one(const __half* __restrict__ Ahi, const __half* __restrict__ Alo,
              int lda, const __half* __restrict__ Bh,
              float* __restrict__ C, __half* __restrict__ Chi,
              __half* __restrict__ Clo, int N, int K, int ldc, int c0)
{
    extern __shared__ char smraw[];
    gemm_body(cvta_s(smraw), Ahi, Alo, lda, Bh, C, Chi, Clo,
              N, K, ldc, blockIdx.y * 128, blockIdx.x * 128, c0);
}

__global__ __launch_bounds__(256, 2)
void gemm_two(const __half* A1h, const __half* A1l, int lda1, const __half* B1,
              float* C1, int N1, int K1, int ldc1,
              const __half* A2h, const __half* A2l, int lda2, const __half* B2,
              float* C2, int N2, int K2, int ldc2, int bx_split)
{
    extern __shared__ char smraw[];
    const uint32_t sb = cvta_s(smraw);
    if ((int)blockIdx.x < bx_split)
        gemm_body(sb, A1h, A1l, lda1, B1, C1, nullptr, nullptr,
                  N1, K1, ldc1, blockIdx.y * 128, blockIdx.x * 128, 0);
    else
        gemm_body(sb, A2h, A2l, lda2, B2, C2, nullptr, nullptr,
                  N2, K2, ldc2, blockIdx.y * 128, (blockIdx.x - bx_split) * 128, 0);
}

// ---------------------------------------------------------------------------
// Grouped fp32 -> fp16 conversion + rope table — identical to R10
// ---------------------------------------------------------------------------
union HV4 { __half h[4]; ushort4 u; };

#define NV4_X   (MROWS * EMB / 4)
#define NV4_QA  (QRANK * EMB / 4)
#define NV4_KVA (576 * EMB / 4)
#define NV4_QB  ((NHEAD * QK_D) * QRANK / 4)
#define NV4_KVB (3072 * KVRANK / 4)
#define NV4_OW  (EMB * (NHEAD * V_D) / 4)
#define C1_ (NV4_X)
#define C2_ (C1_ + NV4_QA)
#define C3_ (C2_ + NV4_KVA)
#define C4_ (C3_ + NV4_QB)
#define C5_ (C4_ + NV4_KVB)
#define C6_ (C5_ + NV4_OW)
#define C7_ (C6_ + SLEN * 32)
#define SPLIT_BLOCKS ((C7_ + 255) / 256)

__global__ void split_all(const float* __restrict__ x,  const float* __restrict__ qa,
                          const float* __restrict__ kva, const float* __restrict__ qb,
                          const float* __restrict__ kvb, const float* __restrict__ ow,
                          __half* __restrict__ xh,  __half* __restrict__ xl,
                          __half* __restrict__ qkh, __half* __restrict__ qbh,
                          __half* __restrict__ kvbh, __half* __restrict__ owh,
                          float2* __restrict__ rope)
{
    const int i = blockIdx.x * blockDim.x + threadIdx.x;
    if (i >= C7_) return;

    if (i >= C6_) {
        const int e = i - C6_;
        const int s = e >> 5, t = e & 31;
        const float theta = powf(10000.f, -((float)(2 * t)) / 64.f);
        float sn, cs;
        sincosf((float)s * theta, &sn, &cs);
        rope[e] = make_float2(cs, sn);
        return;
    }

    const float* src; __half* hi; int o; bool do_lo = false;
    if (i < C1_)      { src = x;   hi = xh;   o = i;       do_lo = true; }
    else if (i < C2_) { src = qa;  hi = qkh;  o = i - C1_; }
    else if (i < C3_) { src = kva; hi = qkh + (size_t)QRANK * EMB; o = i - C2_; }
    else if (i < C4_) { src = qb;  hi = qbh;  o = i - C3_; }
    else if (i < C5_) { src = kvb; hi = kvbh; o = i - C4_; }
    else              { src = ow;  hi = owh;  o = i - C5_; }

    const float4 v = ((const float4*)src)[o];
    const float vv[4] = { v.x, v.y, v.z, v.w };
    HV4 H;
    #pragma unroll
    for (int j = 0; j < 4; ++j) H.h[j] = __float2half_rn(vv[j]);
    ((ushort4*)hi)[o] = H.u;
    if (do_lo) {
        HV4 L;
        #pragma unroll
        for (int j = 0; j < 4; ++j)
            L.h[j] = __float2half_rn(vv[j] - __half2float(H.h[j]));
        ((ushort4*)xl)[o] = L.u;
    }
}

// ---------------------------------------------------------------------------
// Fused repack (q + k + v-transpose) — identical to R10
// ---------------------------------------------------------------------------
__global__ __launch_bounds__(1024)
void repack_all(const float* __restrict__ Q, const float* __restrict__ KVB,
                const float* __restrict__ XC, const float2* __restrict__ rope,
                __half* __restrict__ Qh, __half* __restrict__ Ql,
                __half* __restrict__ Kh, __half* __restrict__ Vh)
{
    __shared__ float tile[64][132];
    const int bb = blockIdx.x;
    const int tid = threadIdx.x;

    if (bb < 2 * MROWS) {
        const bool is_q = bb < MROWS;
        const int bs = is_q ? bb : bb - MROWS;
        const int b  = bs >> 11;
        const int s  = bs & 2047;
        const int h  = tid >> 6;
        const int t  = tid & 63;
        const size_t dst = ((size_t)(b * NHEAD + h) * SLEN + s) * QK_D;

        if (is_q) {
            const float* src = Q + (size_t)bs * (NHEAD * QK_D) + h * QK_D;
            {
                const float v = src[t];
                const __half hv = __float2half_rn(v);
                Qh[dst + t] = hv;
                Ql[dst + t] = __float2half_rn(v - __half2float(hv));
            }
            if (t < 32) {
                const float2 cs = rope[s * 32 + t];
                const float x0 = src[64 + 2 * t];
                const float x1 = src[64 + 2 * t + 1];
                const float r0 = x0 * cs.x - x1 * cs.y;
                const float r1 = x1 * cs.x + x0 * cs.y;
                const __half h0 = __float2half_rn(r0);
                const __half h1 = __float2half_rn(r1);
                Qh[dst + 64 + 2 * t]     = h0;
                Qh[dst + 64 + 2 * t + 1] = h1;
                Ql[dst + 64 + 2 * t]     = __float2half_rn(r0 - __half2float(h0));
                Ql[dst + 64 + 2 * t + 1] = __float2half_rn(r1 - __half2float(h1));
            }
        } else {
            const float* kv = KVB + (size_t)bs * 3072 + h * 192;
            Kh[dst + t] = __float2half_rn(kv[t]);
            if (t < 32) {
                const float2 cs = rope[s * 32 + t];
                const float* kr = XC + (size_t)bs * NXC + 2048;
                const float x0 = kr[2 * t];
                const float x1 = kr[2 * t + 1];
                Kh[dst + 64 + 2 * t]     = __float2half_rn(x0 * cs.x - x1 * cs.y);
                Kh[dst + 64 + 2 * t + 1] = __float2half_rn(x1 * cs.x + x0 * cs.y);
            }
        }
    } else {
        const int idx = bb - 2 * MROWS;
        const int bh  = idx >> 5;
        const int s0  = (idx & 31) * 64;
        const int b   = bh >> 4;
        const int h   = bh & 15;

        #pragma unroll
        for (int p = 0; p < 2; ++p) {
            const int r = p * 32 + (tid >> 5);
            const int c = (tid & 31) * 4;
            const float4 v = *(const float4*)(KVB + (size_t)(b * SLEN + s0 + r) * 3072
                                              + h * 192 + 64 + c);
            tile[r][c + 0] = v.x;
            tile[r][c + 1] = v.y;
            tile[r][c + 2] = v.z;
            tile[r][c + 3] = v.w;
        }
        __syncthreads();

        const int d = tid >> 3;
        const int chunk = tid & 7;
        const size_t obase = ((size_t)bh * 128 + d) * SLEN + s0 + chunk * 8;
        #pragma unroll
        for (int j = 0; j < 8; j += 2) {
            *(uint32_t*)(Vh + obase + j) = pack_h2(tile[chunk * 8 + j][d],
                                                   tile[chunk * 8 + j + 1][d]);
        }
    }
}

// ---------------------------------------------------------------------------
// Flash attention — occ 3: Q staged through KV buffers (smem 71.7KB/CTA).
// Inner-loop arithmetic identical to R10.
// ---------------------------------------------------------------------------
#define QLDE 136
#define VLDE 72
#define STG_SZ 35840               // K (17408) + V (18432)
#define SOFF_KH 0
#define SOFF_VH 17408
#define FLASH_SMEM (2 * STG_SZ)    // 71680 -> 3 CTAs/SM

__device__ __forceinline__ void fa_load_kv(
    uint32_t base, const __half* Kh, const __half* Vh, int bh, int kt, int tid)
{
    const size_t gk = ((size_t)bh * SLEN + kt * 64) * QK_D;
    #pragma unroll
    for (int i = tid; i < 1024; i += 128) {
        const int r = i >> 4, c = (i & 15) * 8;
        cp16(base + SOFF_KH + (uint32_t)(r * QLDE + c) * 2,
             Kh + gk + (size_t)r * QK_D + c);
    }
    const size_t gv = (size_t)bh * V_D * SLEN + kt * 64;
    #pragma unroll
    for (int i = tid; i < 1024; i += 128) {
        const int r = i >> 3, c = (i & 7) * 8;
        cp16(base + SOFF_VH + (uint32_t)(r * VLDE + c) * 2,
             Vh + gv + (size_t)r * SLEN + c);
    }
}

__global__ __launch_bounds__(128, 3)
void flash_mma(const __half* __restrict__ Qh, const __half* __restrict__ Ql,
               const __half* __restrict__ Kh, const __half* __restrict__ Vh,
               __half* __restrict__ Ohi, __half* __restrict__ Olo)
{
    extern __shared__ char smraw[];
    const uint32_t sb0 = cvta_s(smraw);

    const int tid  = threadIdx.x;
    const int wid  = tid >> 5;
    const int lane = tid & 31;
    const int bh = blockIdx.y;
    const int b  = bh >> 4;
    const int h  = bh & 15;
    const int q0 = blockIdx.x * 64;
    const int r_base = wid * 16;

    // ---- stage Q-hi into buffer 0, Q-lo into buffer 1 (dead after frags) ----
    const size_t gq = ((size_t)bh * SLEN + q0) * QK_D;
    #pragma unroll
    for (int i = tid; i < 1024; i += 128) {
        const int r = i >> 4, c = (i & 15) * 8;
        const uint32_t so = (uint32_t)(r * QLDE + c) * 2;
        cp16(sb0 + so,          Qh + gq + (size_t)r * QK_D + c);
        cp16(sb0 + STG_SZ + so, Ql + gq + (size_t)r * QK_D + c);
    }
    cp_commit();
    asm volatile("cp.async.wait_group 0;" ::: "memory");
    __syncthreads();

    uint32_t qfh[8][4], qfl[8][4];
    {
        const int ar = lane & 15;
        const int ac = ((lane >> 4) & 1) * 8;
        #pragma unroll
        for (int kf = 0; kf < 8; ++kf) {
            const uint32_t off = (uint32_t)((r_base + ar) * QLDE + kf * 16 + ac) * 2;
            ldm_x4(qfh[kf], sb0 + off);
            ldm_x4(qfl[kf], sb0 + STG_SZ + off);
        }
    }
    __syncthreads();   // all warps done reading Q from the staging buffers

    // ---- start KV pipeline (stage kt&1) ----
    fa_load_kv(sb0, Kh, Vh, bh, 0, tid);
    cp_commit();

    float Oa[16][4];
    #pragma unroll
    for (int i = 0; i < 16; ++i)
        #pragma unroll
        for (int j = 0; j < 4; ++j) Oa[i][j] = 0.f;
    float m0 = -INFINITY, m1 = -INFINITY, l0 = 0.f, l1 = 0.f;

    const int krow = lane & 7;
    const int kcol = ((lane >> 3) & 3) * 8;

    for (int kt = 0; kt < SLEN / 64; ++kt) {
        if (kt + 1 < SLEN / 64) {
            fa_load_kv(sb0 + ((kt + 1) & 1) * STG_SZ, Kh, Vh, bh, kt + 1, tid);
            cp_commit();
            asm volatile("cp.async.wait_group 1;" ::: "memory");
        } else {
            asm volatile("cp.async.wait_group 0;" ::: "memory");
        }
        __syncthreads();

        const uint32_t sk = sb0 + (kt & 1) * STG_SZ;

        float S[8][4];
        #pragma unroll
        for (int i = 0; i < 8; ++i)
            #pragma unroll
            for (int j = 0; j < 4; ++j) S[i][j] = 0.f;

        #pragma unroll
        for (int nb = 0; nb < 8; ++nb) {
            #pragma unroll
            for (int kfp = 0; kfp < 4; ++kfp) {
                const uint32_t ko = (uint32_t)((nb * 8 + krow) * QLDE
                                               + kfp * 32 + kcol) * 2;
                uint32_t kfh[4];
                ldm_x4(kfh, sk + SOFF_KH + ko);
                mma_f16(S[nb], qfh[2 * kfp],     kfh);
                mma_f16(S[nb], qfh[2 * kfp + 1], kfh + 2);
                mma_f16(S[nb], qfl[2 * kfp],     kfh);
                mma_f16(S[nb], qfl[2 * kfp + 1], kfh + 2);
            }
        }

        float mx0 = -INFINITY, mx1 = -INFINITY;
        #pragma unroll
        for (int nb = 0; nb < 8; ++nb) {
            mx0 = fmaxf(mx0, fmaxf(S[nb][0], S[nb][1]));
            mx1 = fmaxf(mx1, fmaxf(S[nb][2], S[nb][3]));
        }
        mx0 = fmaxf(mx0, __shfl_xor_sync(0xffffffffu, mx0, 1));
        mx0 = fmaxf(mx0, __shfl_xor_sync(0xffffffffu, mx0, 2));
        mx1 = fmaxf(mx1, __shfl_xor_sync(0xffffffffu, mx1, 1));
        mx1 = fmaxf(mx1, __shfl_xor_sync(0xffffffffu, mx1, 2));

        const float mn0 = fmaxf(m0, mx0);
        const float mn1 = fmaxf(m1, mx1);
        const float f0 = __expf(m0 - mn0);
        const float f1 = __expf(m1 - mn1);
        m0 = mn0; m1 = mn1;

        float rs0 = 0.f, rs1 = 0.f;
        #pragma unroll
        for (int nb = 0; nb < 8; ++nb) {
            S[nb][0] = __expf(S[nb][0] - mn0);
            S[nb][1] = __expf(S[nb][1] - mn0);
            S[nb][2] = __expf(S[nb][2] - mn1);
            S[nb][3] = __expf(S[nb][3] - mn1);
            rs0 += S[nb][0] + S[nb][1];
            rs1 += S[nb][2] + S[nb][3];
        }
        rs0 += __shfl_xor_sync(0xffffffffu, rs0, 1);
        rs0 += __shfl_xor_sync(0xffffffffu, rs0, 2);
        rs1 += __shfl_xor_sync(0xffffffffu, rs1, 1);
        rs1 += __shfl_xor_sync(0xffffffffu, rs1, 2);
        l0 = l0 * f0 + rs0;
        l1 = l1 * f1 + rs1;

        #pragma unroll
        for (int i = 0; i < 16; ++i) {
            Oa[i][0] *= f0; Oa[i][1] *= f0;
            Oa[i][2] *= f1; Oa[i][3] *= f1;
        }

        uint32_t ph[4][4], pl[4][4];
        #pragma unroll
        for (int kf2 = 0; kf2 < 4; ++kf2) {
            const float* s0p = S[2 * kf2];
            const float* s1p = S[2 * kf2 + 1];
            ph[kf2][0] = pack_h2(s0p[0], s0p[1]);
            ph[kf2][1] = pack_h2(s0p[2], s0p[3]);
            ph[kf2][2] = pack_h2(s1p[0], s1p[1]);
            ph[kf2][3] = pack_h2(s1p[2], s1p[3]);
            pl[kf2][0] = pack_h2(h_res(s0p[0]), h_res(s0p[1]));
            pl[kf2][1] = pack_h2(h_res(s0p[2]), h_res(s0p[3]));
            pl[kf2][2] = pack_h2(h_res(s1p[0]), h_res(s1p[1]));
            pl[kf2][3] = pack_h2(h_res(s1p[2]), h_res(s1p[3]));
        }

        #pragma unroll
        for (int nb2 = 0; nb2 < 16; ++nb2) {
            #pragma unroll
            for (int kfp2 = 0; kfp2 < 2; ++kfp2) {
                const uint32_t vo = (uint32_t)((nb2 * 8 + krow) * VLDE
                                               + kfp2 * 32 + kcol) * 2;
                uint32_t vfh[4];
                ldm_x4(vfh, sk + SOFF_VH + vo);
                mma_f16(Oa[nb2], ph[2 * kfp2],     vfh);
                mma_f16(Oa[nb2], ph[2 * kfp2 + 1], vfh + 2);
                mma_f16(Oa[nb2], pl[2 * kfp2],     vfh);
                mma_f16(Oa[nb2], pl[2 * kfp2 + 1], vfh + 2);
            }
        }
        __syncthreads();
    }

    const float inv0 = 1.f / l0;
    const float inv1 = 1.f / l1;
    const int er = lane >> 2;
    const int ec = (lane & 3) * 2;
    const size_t row0 = (size_t)(b * SLEN + q0 + r_base + er) * (NHEAD * V_D) + h * V_D;
    const size_t row1 = row0 + (size_t)8 * (NHEAD * V_D);
    #pragma unroll
    for (int nb2 = 0; nb2 < 16; ++nb2) {
        const int col = nb2 * 8 + ec;
        const float a0 = Oa[nb2][0] * inv0, a1 = Oa[nb2][1] * inv0;
        const float a2 = Oa[nb2][2] * inv1, a3 = Oa[nb2][3] * inv1;
        *(uint32_t*)(Ohi + row0 + col) = pack_h2(a0, a1);
        *(uint32_t*)(Olo + row0 + col) = pack_h2(h_res(a0), h_res(a1));
        *(uint32_t*)(Ohi + row1 + col) = pack_h2(a2, a3);
        *(uint32_t*)(Olo + row1 + col) = pack_h2(h_res(a2), h_res(a3));
    }
}

// ---------------------------------------------------------------------------
extern "C" void kernel_launch(void* const* d_in, const int* in_sizes, int n_in,
                              void* d_out, int out_size)
{
    const float* x    = (const float*)d_in[0];
    const float* q_a  = (const float*)d_in[1];
    const float* q_b  = (const float*)d_in[2];
    const float* kv_a = (const float*)d_in[3];
    const float* kv_b = (const float*)d_in[4];
    const float* o_w  = (const float*)d_in[5];
    float* out = (float*)d_out;

    float *XC, *Q, *KVB;
    float2* rope;
    cudaGetSymbolAddress((void**)&XC,   g_XC);
    cudaGetSymbolAddress((void**)&Q,    g_Q);
    cudaGetSymbolAddress((void**)&KVB,  g_KVB);
    cudaGetSymbolAddress((void**)&rope, g_rope);

    __half *x_hi, *x_lo, *qk_h, *qb_h, *kvb_h, *ow_h, *XC_hi, *XC_lo;
    __half *Qb_hi, *Qb_lo, *Kb_h, *Vt_h, *O_hi, *O_lo;
    cudaGetSymbolAddress((void**)&x_hi,  g_x_hi);
    cudaGetSymbolAddress((void**)&x_lo,  g_x_lo);
    cudaGetSymbolAddress((void**)&qk_h,  g_qakva_h);
    cudaGetSymbolAddress((void**)&qb_h,  g_qb_h);
    cudaGetSymbolAddress((void**)&kvb_h, g_kvb_h);
    cudaGetSymbolAddress((void**)&ow_h,  g_ow_h);
    cudaGetSymbolAddress((void**)&XC_hi, g_XC_hi);
    cudaGetSymbolAddress((void**)&XC_lo, g_XC_lo);
    cudaGetSymbolAddress((void**)&Qb_hi, g_Qb_hi);
    cudaGetSymbolAddress((void**)&Qb_lo, g_Qb_lo);
    cudaGetSymbolAddress((void**)&Kb_h,  g_Kb_h);
    cudaGetSymbolAddress((void**)&Vt_h,  g_Vt_h);
    cudaGetSymbolAddress((void**)&O_hi,  g_O_hi);
    cudaGetSymbolAddress((void**)&O_lo,  g_O_lo);

    cudaFuncSetAttribute(gemm_one, cudaFuncAttributeMaxDynamicSharedMemorySize,
                         GEMM_SMEM);
    cudaFuncSetAttribute(gemm_two, cudaFuncAttributeMaxDynamicSharedMemorySize,
                         GEMM_SMEM);
    cudaFuncSetAttribute(flash_mma, cudaFuncAttributeMaxDynamicSharedMemorySize,
                         FLASH_SMEM);

    // 1) conversions + rope table (single launch)
    split_all<<<SPLIT_BLOCKS, 256>>>(x, q_a, kv_a, q_b, kv_b, o_w,
                                     x_hi, x_lo, qk_h, qb_h, kvb_h, ow_h, rope);

    // 2) merged x-GEMM: XC = x @ [q_a; kv_a]^T (fp32 only for k_rot cols >=2048)
    gemm_one<<<dim3(17, 32), 256, GEMM_SMEM>>>(x_hi, x_lo, EMB, qk_h,
                                               XC, XC_hi, XC_lo, NXC, EMB, NXC, 2048);

    // 3) grouped: Q = Xq @ q_b^T  +  KVB = ckv512 @ kv_b^T
    gemm_two<<<dim3(16 + 24, 32), 256, GEMM_SMEM>>>(
        XC_hi, XC_lo, NXC, qb_h, Q, 2048, QRANK, 2048,
        XC_hi + QRANK, XC_lo + QRANK, NXC, kvb_h, KVB, 3072, KVRANK, 3072,
        16);

    // 4) fused repack
    repack_all<<<2 * MROWS + 1024, 1024>>>(Q, KVB, XC, rope,
                                           Qb_hi, Qb_lo, Kb_h, Vt_h);

    // 5) attention: occ 3 (smem 71.7KB), KV double-buffered
    flash_mma<<<dim3(SLEN / 64, BHN), 128, FLASH_SMEM>>>(
        Qb_hi, Qb_lo, Kb_h, Vt_h, O_hi, O_lo);

    // 6) out = O @ o_w^T
    gemm_one<<<dim3(16, 32), 256, GEMM_SMEM>>>(O_hi, O_lo, EMB, ow_h,
                                               out, nullptr, nullptr,
                                               EMB, NHEAD * V_D, EMB, 0);
}

// round 12
// speedup vs baseline: 1.1015x; 1.1015x over previous
#include <cuda_runtime.h>
#include <cuda_fp16.h>
#include <math.h>
#include <stdint.h>

// ---------------------------------------------------------------------------
// Problem constants
// ---------------------------------------------------------------------------
#define BATCH   2
#define SLEN    2048
#define EMB     2048
#define NHEAD   16
#define QRANK   1536
#define KVRANK  512
#define QK_D    128
#define V_D     128
#define MROWS   (BATCH * SLEN)        // 4096
#define BHN     (BATCH * NHEAD)       // 32
#define NXC     (QRANK + 576)         // 2112

// ------------------------- fp32 scratch -----------------------------------
__device__ float  g_XC [(size_t)MROWS * NXC];           // only cols >=2048 written/read
__device__ float  g_Q  [(size_t)MROWS * (NHEAD * QK_D)];
__device__ float  g_KVB[(size_t)MROWS * 3072];
__device__ float2 g_rope[SLEN * 32];                    // (cos, sin)

// ------------------------- fp16 buffers -----------------------------------
__device__ __half g_x_hi   [(size_t)MROWS * EMB];
__device__ __half g_x_lo   [(size_t)MROWS * EMB];
__device__ __half g_qakva_h[(size_t)NXC * EMB];
__device__ __half g_qb_h   [(size_t)(NHEAD * QK_D) * QRANK];
__device__ __half g_kvb_h  [(size_t)3072 * KVRANK];
__device__ __half g_ow_h   [(size_t)EMB * (NHEAD * V_D)];
__device__ __half g_XC_hi  [(size_t)MROWS * NXC];
__device__ __half g_XC_lo  [(size_t)MROWS * NXC];
__device__ __half g_Qb_hi  [(size_t)BHN * SLEN * QK_D];
__device__ __half g_Qb_lo  [(size_t)BHN * SLEN * QK_D];
__device__ __half g_Kb_h   [(size_t)BHN * SLEN * QK_D];
__device__ __half g_Vt_h   [(size_t)BHN * V_D * SLEN];
__device__ __half g_O_hi   [(size_t)MROWS * (NHEAD * V_D)];
__device__ __half g_O_lo   [(size_t)MROWS * (NHEAD * V_D)];

// ---------------------------------------------------------------------------
// PTX helpers
// ---------------------------------------------------------------------------
__device__ __forceinline__ uint32_t cvta_s(const void* p) {
    return (uint32_t)__cvta_generic_to_shared(p);
}
__device__ __forceinline__ void cp16(uint32_t dst, const void* src) {
    asm volatile("cp.async.cg.shared.global [%0], [%1], 16;"
                 :: "r"(dst), "l"(src) : "memory");
}
__device__ __forceinline__ void cp16_pred(uint32_t dst, const void* src, bool valid) {
    const int sz = valid ? 16 : 0;
    asm volatile("cp.async.cg.shared.global [%0], [%1], 16, %2;"
                 :: "r"(dst), "l"(src), "r"(sz) : "memory");
}
__device__ __forceinline__ void cp_commit() {
    asm volatile("cp.async.commit_group;" ::: "memory");
}
__device__ __forceinline__ void ldm_x4(uint32_t* r, uint32_t addr) {
    asm volatile("ldmatrix.sync.aligned.m8n8.x4.shared.b16 {%0,%1,%2,%3}, [%4];"
                 : "=r"(r[0]), "=r"(r[1]), "=r"(r[2]), "=r"(r[3]) : "r"(addr));
}
__device__ __forceinline__ void ldm_x2(uint32_t& r0, uint32_t& r1, uint32_t addr) {
    asm volatile("ldmatrix.sync.aligned.m8n8.x2.shared.b16 {%0,%1}, [%2];"
                 : "=r"(r0), "=r"(r1) : "r"(addr));
}
__device__ __forceinline__ void mma_f16(float* c, const uint32_t* a,
                                        const uint32_t* b) {
    asm volatile(
        "mma.sync.aligned.m16n8k16.row.col.f32.f16.f16.f32 "
        "{%0,%1,%2,%3}, {%4,%5,%6,%7}, {%8,%9}, {%0,%1,%2,%3};"
        : "+f"(c[0]), "+f"(c[1]), "+f"(c[2]), "+f"(c[3])
        : "r"(a[0]), "r"(a[1]), "r"(a[2]), "r"(a[3]), "r"(b[0]), "r"(b[1]));
}
__device__ __forceinline__ uint32_t pack_h2(float lo, float hi) {
    uint32_t r;
    asm("cvt.rn.f16x2.f32 %0, %1, %2;" : "=r"(r) : "f"(hi), "f"(lo));
    return r;
}
__device__ __forceinline__ float h_res(float v) {
    return v - __half2float(__float2half_rn(v));
}

// ---------------------------------------------------------------------------
// HMMA 2-term fp16 GEMM (NT) — identical to R10
// ---------------------------------------------------------------------------
#define LDP 40
#define TILE_B (128 * LDP * 2)
#define STAGE_B (3 * TILE_B)
#define GEMM_SMEM (2 * STAGE_B)

__device__ __forceinline__ void gload_stage(
    uint32_t sb, const __half* Ahi, const __half* Alo, int lda,
    const __half* Bh, int bm, int bn, int k0, int K, int N, int tid)
{
    #pragma unroll
    for (int idx = tid; idx < 512; idx += 256) {
        const int r = idx >> 2, c = idx & 3;
        const uint32_t so = (uint32_t)(r * LDP * 2 + c * 16);
        const size_t ga = (size_t)(bm + r) * lda + k0 + c * 8;
        cp16(sb + 0 * TILE_B + so, Ahi + ga);
        cp16(sb + 1 * TILE_B + so, Alo + ga);
        const bool v = (bn + r) < N;
        const size_t gb = v ? ((size_t)(bn + r) * K + k0 + c * 8) : 0;
        cp16_pred(sb + 2 * TILE_B + so, Bh + gb, v);
    }
}

__device__ __forceinline__ void gemm_body(
    uint32_t sbase,
    const __half* __restrict__ Ahi, const __half* __restrict__ Alo, int lda,
    const __half* __restrict__ Bh,
    float* __restrict__ C, __half* __restrict__ Chi, __half* __restrict__ Clo,
    int N, int K, int ldc, int bm, int bn, int c0)
{
    const int tid  = threadIdx.x;
    const int wid  = tid >> 5;
    const int lane = tid & 31;
    const int warp_m = (wid >> 2) * 64;
    const int warp_n = (wid & 3) * 32;
    const int nk = K / 32;

    float acc[4][4][4];
    #pragma unroll
    for (int i = 0; i < 4; ++i)
        #pragma unroll
        for (int j = 0; j < 4; ++j)
            #pragma unroll
            for (int q = 0; q < 4; ++q) acc[i][j][q] = 0.f;

    gload_stage(sbase, Ahi, Alo, lda, Bh, bm, bn, 0, K, N, tid);
    cp_commit();

    const int a_row = lane & 15;
    const int a_coff = (lane >> 4) << 3;
    const int b_row = lane & 7;
    const int b_coff = ((lane >> 3) & 1) << 3;

    for (int i = 0; i < nk; ++i) {
        if (i + 1 < nk) {
            gload_stage(sbase + ((i + 1) & 1) * STAGE_B, Ahi, Alo, lda, Bh,
                        bm, bn, (i + 1) * 32, K, N, tid);
            cp_commit();
            asm volatile("cp.async.wait_group 1;" ::: "memory");
        } else {
            asm volatile("cp.async.wait_group 0;" ::: "memory");
        }
        __syncthreads();

        const uint32_t sb = sbase + (i & 1) * STAGE_B;
        #pragma unroll
        for (int kc = 0; kc < 2; ++kc) {
            const int kel = kc * 16;
            uint32_t ah[4][4], al[4][4];
            #pragma unroll
            for (int mi = 0; mi < 4; ++mi) {
                const uint32_t ao = (uint32_t)((warp_m + mi * 16 + a_row) * LDP
                                               + kel + a_coff) * 2;
                ldm_x4(ah[mi], sb + ao);
                ldm_x4(al[mi], sb + TILE_B + ao);
            }
            #pragma unroll
            for (int ni = 0; ni < 4; ++ni) {
                const uint32_t bo = (uint32_t)((warp_n + ni * 8 + b_row) * LDP
                                               + kel + b_coff) * 2;
                uint32_t bh[2];
                ldm_x2(bh[0], bh[1], sb + 2 * TILE_B + bo);
                #pragma unroll
                for (int mi = 0; mi < 4; ++mi) {
                    mma_f16(acc[mi][ni], ah[mi], bh);
                    mma_f16(acc[mi][ni], al[mi], bh);
                }
            }
        }
        __syncthreads();
    }

    const int er = lane >> 2;
    const int ec = (lane & 3) * 2;
    #pragma unroll
    for (int mi = 0; mi < 4; ++mi) {
        #pragma unroll
        for (int ni = 0; ni < 4; ++ni) {
            const int col = bn + warp_n + ni * 8 + ec;
            if (col < N) {
                const int r0 = bm + warp_m + mi * 16 + er;
                const float a0 = acc[mi][ni][0], a1 = acc[mi][ni][1];
                const float a2 = acc[mi][ni][2], a3 = acc[mi][ni][3];
                if (C && col >= c0) {
                    *(float2*)(C + (size_t)r0 * ldc + col) = make_float2(a0, a1);
                    *(float2*)(C + (size_t)(r0 + 8) * ldc + col) = make_float2(a2, a3);
                }
                if (Chi) {
                    *(uint32_t*)(Chi + (size_t)r0 * ldc + col) = pack_h2(a0, a1);
                    *(uint32_t*)(Clo + (size_t)r0 * ldc + col) =
                        pack_h2(h_res(a0), h_res(a1));
                    *(uint32_t*)(Chi + (size_t)(r0 + 8) * ldc + col) = pack_h2(a2, a3);
                    *(uint32_t*)(Clo + (size_t)(r0 + 8) * ldc + col) =
                        pack_h2(h_res(a2), h_res(a3));
                }
            }
        }
    }
}

__global__ __launch_bounds__(256, 2)
void gemm_one(const __half* __restrict__ Ahi, const __half* __restrict__ Alo,
              int lda, const __half* __restrict__ Bh,
              float* __restrict__ C, __half* __restrict__ Chi,
              __half* __restrict__ Clo, int N, int K, int ldc, int c0)
{
    extern __shared__ char smraw[];
    gemm_body(cvta_s(smraw), Ahi, Alo, lda, Bh, C, Chi, Clo,
              N, K, ldc, blockIdx.y * 128, blockIdx.x * 128, c0);
}

__global__ __launch_bounds__(256, 2)
void gemm_two(const __half* A1h, const __half* A1l, int lda1, const __half* B1,
              float* C1, int N1, int K1, int ldc1,
              const __half* A2h, const __half* A2l, int lda2, const __half* B2,
              float* C2, int N2, int K2, int ldc2, int bx_split)
{
    extern __shared__ char smraw[];
    const uint32_t sb = cvta_s(smraw);
    if ((int)blockIdx.x < bx_split)
        gemm_body(sb, A1h, A1l, lda1, B1, C1, nullptr, nullptr,
                  N1, K1, ldc1, blockIdx.y * 128, blockIdx.x * 128, 0);
    else
        gemm_body(sb, A2h, A2l, lda2, B2, C2, nullptr, nullptr,
                  N2, K2, ldc2, blockIdx.y * 128, (blockIdx.x - bx_split) * 128, 0);
}

// ---------------------------------------------------------------------------
// Grouped fp32 -> fp16 conversion + rope table — identical to R10
// ---------------------------------------------------------------------------
union HV4 { __half h[4]; ushort4 u; };

#define NV4_X   (MROWS * EMB / 4)
#define NV4_QA  (QRANK * EMB / 4)
#define NV4_KVA (576 * EMB / 4)
#define NV4_QB  ((NHEAD * QK_D) * QRANK / 4)
#define NV4_KVB (3072 * KVRANK / 4)
#define NV4_OW  (EMB * (NHEAD * V_D) / 4)
#define C1_ (NV4_X)
#define C2_ (C1_ + NV4_QA)
#define C3_ (C2_ + NV4_KVA)
#define C4_ (C3_ + NV4_QB)
#define C5_ (C4_ + NV4_KVB)
#define C6_ (C5_ + NV4_OW)
#define C7_ (C6_ + SLEN * 32)
#define SPLIT_BLOCKS ((C7_ + 255) / 256)

__global__ void split_all(const float* __restrict__ x,  const float* __restrict__ qa,
                          const float* __restrict__ kva, const float* __restrict__ qb,
                          const float* __restrict__ kvb, const float* __restrict__ ow,
                          __half* __restrict__ xh,  __half* __restrict__ xl,
                          __half* __restrict__ qkh, __half* __restrict__ qbh,
                          __half* __restrict__ kvbh, __half* __restrict__ owh,
                          float2* __restrict__ rope)
{
    const int i = blockIdx.x * blockDim.x + threadIdx.x;
    if (i >= C7_) return;

    if (i >= C6_) {
        const int e = i - C6_;
        const int s = e >> 5, t = e & 31;
        const float theta = powf(10000.f, -((float)(2 * t)) / 64.f);
        float sn, cs;
        sincosf((float)s * theta, &sn, &cs);
        rope[e] = make_float2(cs, sn);
        return;
    }

    const float* src; __half* hi; int o; bool do_lo = false;
    if (i < C1_)      { src = x;   hi = xh;   o = i;       do_lo = true; }
    else if (i < C2_) { src = qa;  hi = qkh;  o = i - C1_; }
    else if (i < C3_) { src = kva; hi = qkh + (size_t)QRANK * EMB; o = i - C2_; }
    else if (i < C4_) { src = qb;  hi = qbh;  o = i - C3_; }
    else if (i < C5_) { src = kvb; hi = kvbh; o = i - C4_; }
    else              { src = ow;  hi = owh;  o = i - C5_; }

    const float4 v = ((const float4*)src)[o];
    const float vv[4] = { v.x, v.y, v.z, v.w };
    HV4 H;
    #pragma unroll
    for (int j = 0; j < 4; ++j) H.h[j] = __float2half_rn(vv[j]);
    ((ushort4*)hi)[o] = H.u;
    if (do_lo) {
        HV4 L;
        #pragma unroll
        for (int j = 0; j < 4; ++j)
            L.h[j] = __float2half_rn(vv[j] - __half2float(H.h[j]));
        ((ushort4*)xl)[o] = L.u;
    }
}

// ---------------------------------------------------------------------------
// Fused repack (q + k + v-transpose), pair-vectorized Q/K branches.
// Each thread handles an element PAIR (pass pair for t<32, rope pair for
// t>=32) -> single uint32 store at offset 2t. Same arithmetic as R10.
// ---------------------------------------------------------------------------
__global__ __launch_bounds__(1024)
void repack_all(const float* __restrict__ Q, const float* __restrict__ KVB,
                const float* __restrict__ XC, const float2* __restrict__ rope,
                __half* __restrict__ Qh, __half* __restrict__ Ql,
                __half* __restrict__ Kh, __half* __restrict__ Vh)
{
    __shared__ float tile[64][132];
    const int bb = blockIdx.x;
    const int tid = threadIdx.x;

    if (bb < 2 * MROWS) {
        const bool is_q = bb < MROWS;
        const int bs = is_q ? bb : bb - MROWS;
        const int b  = bs >> 11;
        const int s  = bs & 2047;
        const int h  = tid >> 6;          // 0..15
        const int t  = tid & 63;          // 0..63, pair index = t
        const size_t dst = ((size_t)(b * NHEAD + h) * SLEN + s) * QK_D + 2 * t;

        float v0, v1;
        if (is_q) {
            const float* src = Q + (size_t)bs * (NHEAD * QK_D) + h * QK_D;
            if (t < 32) {                 // pass pair at d = 2t, 2t+1
                const float2 p = *(const float2*)(src + 2 * t);
                v0 = p.x; v1 = p.y;
            } else {                      // rope pair, tr = t-32
                const int tr = t - 32;
                const float2 cs = rope[s * 32 + tr];
                const float2 p = *(const float2*)(src + 64 + 2 * tr);
                v0 = p.x * cs.x - p.y * cs.y;
                v1 = p.y * cs.x + p.x * cs.y;
            }
            *(uint32_t*)(Qh + dst) = pack_h2(v0, v1);
            *(uint32_t*)(Ql + dst) = pack_h2(h_res(v0), h_res(v1));
        } else {
            if (t < 32) {
                const float* kv = KVB + (size_t)bs * 3072 + h * 192;
                const float2 p = *(const float2*)(kv + 2 * t);
                v0 = p.x; v1 = p.y;
            } else {
                const int tr = t - 32;
                const float2 cs = rope[s * 32 + tr];
                const float* kr = XC + (size_t)bs * NXC + 2048;
                const float2 p = *(const float2*)(kr + 2 * tr);
                v0 = p.x * cs.x - p.y * cs.y;
                v1 = p.y * cs.x + p.x * cs.y;
            }
            *(uint32_t*)(Kh + dst) = pack_h2(v0, v1);
        }
    } else {
        const int idx = bb - 2 * MROWS;
        const int bh  = idx >> 5;
        const int s0  = (idx & 31) * 64;
        const int b   = bh >> 4;
        const int h   = bh & 15;

        #pragma unroll
        for (int p = 0; p < 2; ++p) {
            const int r = p * 32 + (tid >> 5);
            const int c = (tid & 31) * 4;
            const float4 v = *(const float4*)(KVB + (size_t)(b * SLEN + s0 + r) * 3072
                                              + h * 192 + 64 + c);
            tile[r][c + 0] = v.x;
            tile[r][c + 1] = v.y;
            tile[r][c + 2] = v.z;
            tile[r][c + 3] = v.w;
        }
        __syncthreads();

        const int d = tid >> 3;
        const int chunk = tid & 7;
        const size_t obase = ((size_t)bh * 128 + d) * SLEN + s0 + chunk * 8;
        #pragma unroll
        for (int j = 0; j < 8; j += 2) {
            *(uint32_t*)(Vh + obase + j) = pack_h2(tile[chunk * 8 + j][d],
                                                   tile[chunk * 8 + j + 1][d]);
        }
    }
}

// ---------------------------------------------------------------------------
// Flash attention — identical to R10 (128 thr, 64-row Q tiles, occ 2)
// ---------------------------------------------------------------------------
#define QLDE 136
#define VLDE 72
#define OFF_QH 0
#define OFF_QL 17408
#define OFF_STG 34816
#define STG_SZ 35840
#define SOFF_KH 0
#define SOFF_VH 17408
#define FLASH_SMEM (OFF_STG + 2 * STG_SZ)   // 106496

__device__ __forceinline__ void fa_load_kv(
    uint32_t base, const __half* Kh, const __half* Vh, int bh, int kt, int tid)
{
    const size_t gk = ((size_t)bh * SLEN + kt * 64) * QK_D;
    #pragma unroll
    for (int i = tid; i < 1024; i += 128) {
        const int r = i >> 4, c = (i & 15) * 8;
        cp16(base + SOFF_KH + (uint32_t)(r * QLDE + c) * 2,
             Kh + gk + (size_t)r * QK_D + c);
    }
    const size_t gv = (size_t)bh * V_D * SLEN + kt * 64;
    #pragma unroll
    for (int i = tid; i < 1024; i += 128) {
        const int r = i >> 3, c = (i & 7) * 8;
        cp16(base + SOFF_VH + (uint32_t)(r * VLDE + c) * 2,
             Vh + gv + (size_t)r * SLEN + c);
    }
}

__global__ __launch_bounds__(128, 2)
void flash_mma(const __half* __restrict__ Qh, const __half* __restrict__ Ql,
               const __half* __restrict__ Kh, const __half* __restrict__ Vh,
               __half* __restrict__ Ohi, __half* __restrict__ Olo)
{
    extern __shared__ char smraw[];
    const uint32_t sb0 = cvta_s(smraw);

    const int tid  = threadIdx.x;
    const int wid  = tid >> 5;
    const int lane = tid & 31;
    const int bh = blockIdx.y;
    const int b  = bh >> 4;
    const int h  = bh & 15;
    const int q0 = blockIdx.x * 64;
    const int r_base = wid * 16;

    const size_t gq = ((size_t)bh * SLEN + q0) * QK_D;
    #pragma unroll
    for (int i = tid; i < 1024; i += 128) {
        const int r = i >> 4, c = (i & 15) * 8;
        const uint32_t so = (uint32_t)(r * QLDE + c) * 2;
        cp16(sb0 + OFF_QH + so, Qh + gq + (size_t)r * QK_D + c);
        cp16(sb0 + OFF_QL + so, Ql + gq + (size_t)r * QK_D + c);
    }
    fa_load_kv(sb0 + OFF_STG, Kh, Vh, bh, 0, tid);
    cp_commit();
    asm volatile("cp.async.wait_group 0;" ::: "memory");
    __syncthreads();

    uint32_t qfh[8][4], qfl[8][4];
    {
        const int ar = lane & 15;
        const int ac = ((lane >> 4) & 1) * 8;
        #pragma unroll
        for (int kf = 0; kf < 8; ++kf) {
            const uint32_t off = (uint32_t)((r_base + ar) * QLDE + kf * 16 + ac) * 2;
            ldm_x4(qfh[kf], sb0 + OFF_QH + off);
            ldm_x4(qfl[kf], sb0 + OFF_QL + off);
        }
    }

    float Oa[16][4];
    #pragma unroll
    for (int i = 0; i < 16; ++i)
        #pragma unroll
        for (int j = 0; j < 4; ++j) Oa[i][j] = 0.f;
    float m0 = -INFINITY, m1 = -INFINITY, l0 = 0.f, l1 = 0.f;

    const int krow = lane & 7;
    const int kcol = ((lane >> 3) & 3) * 8;

    for (int kt = 0; kt < SLEN / 64; ++kt) {
        if (kt + 1 < SLEN / 64) {
            fa_load_kv(sb0 + OFF_STG + ((kt + 1) & 1) * STG_SZ, Kh, Vh, bh, kt + 1, tid);
            cp_commit();
            asm volatile("cp.async.wait_group 1;" ::: "memory");
        } else {
            asm volatile("cp.async.wait_group 0;" ::: "memory");
        }
        __syncthreads();

        const uint32_t sk = sb0 + OFF_STG + (kt & 1) * STG_SZ;

        float S[8][4];
        #pragma unroll
        for (int i = 0; i < 8; ++i)
            #pragma unroll
            for (int j = 0; j < 4; ++j) S[i][j] = 0.f;

        #pragma unroll
        for (int nb = 0; nb < 8; ++nb) {
            #pragma unroll
            for (int kfp = 0; kfp < 4; ++kfp) {
                const uint32_t ko = (uint32_t)((nb * 8 + krow) * QLDE
                                               + kfp * 32 + kcol) * 2;
                uint32_t kfh[4];
                ldm_x4(kfh, sk + SOFF_KH + ko);
                mma_f16(S[nb], qfh[2 * kfp],     kfh);
                mma_f16(S[nb], qfh[2 * kfp + 1], kfh + 2);
                mma_f16(S[nb], qfl[2 * kfp],     kfh);
                mma_f16(S[nb], qfl[2 * kfp + 1], kfh + 2);
            }
        }

        float mx0 = -INFINITY, mx1 = -INFINITY;
        #pragma unroll
        for (int nb = 0; nb < 8; ++nb) {
            mx0 = fmaxf(mx0, fmaxf(S[nb][0], S[nb][1]));
            mx1 = fmaxf(mx1, fmaxf(S[nb][2], S[nb][3]));
        }
        mx0 = fmaxf(mx0, __shfl_xor_sync(0xffffffffu, mx0, 1));
        mx0 = fmaxf(mx0, __shfl_xor_sync(0xffffffffu, mx0, 2));
        mx1 = fmaxf(mx1, __shfl_xor_sync(0xffffffffu, mx1, 1));
        mx1 = fmaxf(mx1, __shfl_xor_sync(0xffffffffu, mx1, 2));

        const float mn0 = fmaxf(m0, mx0);
        const float mn1 = fmaxf(m1, mx1);
        const float f0 = __expf(m0 - mn0);
        const float f1 = __expf(m1 - mn1);
        m0 = mn0; m1 = mn1;

        float rs0 = 0.f, rs1 = 0.f;
        #pragma unroll
        for (int nb = 0; nb < 8; ++nb) {
            S[nb][0] = __expf(S[nb][0] - mn0);
            S[nb][1] = __expf(S[nb][1] - mn0);
            S[nb][2] = __expf(S[nb][2] - mn1);
            S[nb][3] = __expf(S[nb][3] - mn1);
            rs0 += S[nb][0] + S[nb][1];
            rs1 += S[nb][2] + S[nb][3];
        }
        rs0 += __shfl_xor_sync(0xffffffffu, rs0, 1);
        rs0 += __shfl_xor_sync(0xffffffffu, rs0, 2);
        rs1 += __shfl_xor_sync(0xffffffffu, rs1, 1);
        rs1 += __shfl_xor_sync(0xffffffffu, rs1, 2);
        l0 = l0 * f0 + rs0;
        l1 = l1 * f1 + rs1;

        #pragma unroll
        for (int i = 0; i < 16; ++i) {
            Oa[i][0] *= f0; Oa[i][1] *= f0;
            Oa[i][2] *= f1; Oa[i][3] *= f1;
        }

        uint32_t ph[4][4], pl[4][4];
        #pragma unroll
        for (int kf2 = 0; kf2 < 4; ++kf2) {
            const float* s0p = S[2 * kf2];
            const float* s1p = S[2 * kf2 + 1];
            ph[kf2][0] = pack_h2(s0p[0], s0p[1]);
            ph[kf2][1] = pack_h2(s0p[2], s0p[3]);
            ph[kf2][2] = pack_h2(s1p[0], s1p[1]);
            ph[kf2][3] = pack_h2(s1p[2], s1p[3]);
            pl[kf2][0] = pack_h2(h_res(s0p[0]), h_res(s0p[1]));
            pl[kf2][1] = pack_h2(h_res(s0p[2]), h_res(s0p[3]));
            pl[kf2][2] = pack_h2(h_res(s1p[0]), h_res(s1p[1]));
            pl[kf2][3] = pack_h2(h_res(s1p[2]), h_res(s1p[3]));
        }

        #pragma unroll
        for (int nb2 = 0; nb2 < 16; ++nb2) {
            #pragma unroll
            for (int kfp2 = 0; kfp2 < 2; ++kfp2) {
                const uint32_t vo = (uint32_t)((nb2 * 8 + krow) * VLDE
                                               + kfp2 * 32 + kcol) * 2;
                uint32_t vfh[4];
                ldm_x4(vfh, sk + SOFF_VH + vo);
                mma_f16(Oa[nb2], ph[2 * kfp2],     vfh);
                mma_f16(Oa[nb2], ph[2 * kfp2 + 1], vfh + 2);
                mma_f16(Oa[nb2], pl[2 * kfp2],     vfh);
                mma_f16(Oa[nb2], pl[2 * kfp2 + 1], vfh + 2);
            }
        }
        __syncthreads();
    }

    const float inv0 = 1.f / l0;
    const float inv1 = 1.f / l1;
    const int er = lane >> 2;
    const int ec = (lane & 3) * 2;
    const size_t row0 = (size_t)(b * SLEN + q0 + r_base + er) * (NHEAD * V_D) + h * V_D;
    const size_t row1 = row0 + (size_t)8 * (NHEAD * V_D);
    #pragma unroll
    for (int nb2 = 0; nb2 < 16; ++nb2) {
        const int col = nb2 * 8 + ec;
        const float a0 = Oa[nb2][0] * inv0, a1 = Oa[nb2][1] * inv0;
        const float a2 = Oa[nb2][2] * inv1, a3 = Oa[nb2][3] * inv1;
        *(uint32_t*)(Ohi + row0 + col) = pack_h2(a0, a1);
        *(uint32_t*)(Olo + row0 + col) = pack_h2(h_res(a0), h_res(a1));
        *(uint32_t*)(Ohi + row1 + col) = pack_h2(a2, a3);
        *(uint32_t*)(Olo + row1 + col) = pack_h2(h_res(a2), h_res(a3));
    }
}

// ---------------------------------------------------------------------------
extern "C" void kernel_launch(void* const* d_in, const int* in_sizes, int n_in,
                              void* d_out, int out_size)
{
    const float* x    = (const float*)d_in[0];
    const float* q_a  = (const float*)d_in[1];
    const float* q_b  = (const float*)d_in[2];
    const float* kv_a = (const float*)d_in[3];
    const float* kv_b = (const float*)d_in[4];
    const float* o_w  = (const float*)d_in[5];
    float* out = (float*)d_out;

    float *XC, *Q, *KVB;
    float2* rope;
    cudaGetSymbolAddress((void**)&XC,   g_XC);
    cudaGetSymbolAddress((void**)&Q,    g_Q);
    cudaGetSymbolAddress((void**)&KVB,  g_KVB);
    cudaGetSymbolAddress((void**)&rope, g_rope);

    __half *x_hi, *x_lo, *qk_h, *qb_h, *kvb_h, *ow_h, *XC_hi, *XC_lo;
    __half *Qb_hi, *Qb_lo, *Kb_h, *Vt_h, *O_hi, *O_lo;
    cudaGetSymbolAddress((void**)&x_hi,  g_x_hi);
    cudaGetSymbolAddress((void**)&x_lo,  g_x_lo);
    cudaGetSymbolAddress((void**)&qk_h,  g_qakva_h);
    cudaGetSymbolAddress((void**)&qb_h,  g_qb_h);
    cudaGetSymbolAddress((void**)&kvb_h, g_kvb_h);
    cudaGetSymbolAddress((void**)&ow_h,  g_ow_h);
    cudaGetSymbolAddress((void**)&XC_hi, g_XC_hi);
    cudaGetSymbolAddress((void**)&XC_lo, g_XC_lo);
    cudaGetSymbolAddress((void**)&Qb_hi, g_Qb_hi);
    cudaGetSymbolAddress((void**)&Qb_lo, g_Qb_lo);
    cudaGetSymbolAddress((void**)&Kb_h,  g_Kb_h);
    cudaGetSymbolAddress((void**)&Vt_h,  g_Vt_h);
    cudaGetSymbolAddress((void**)&O_hi,  g_O_hi);
    cudaGetSymbolAddress((void**)&O_lo,  g_O_lo);

    cudaFuncSetAttribute(gemm_one, cudaFuncAttributeMaxDynamicSharedMemorySize,
                         GEMM_SMEM);
    cudaFuncSetAttribute(gemm_two, cudaFuncAttributeMaxDynamicSharedMemorySize,
                         GEMM_SMEM);
    cudaFuncSetAttribute(flash_mma, cudaFuncAttributeMaxDynamicSharedMemorySize,
                         FLASH_SMEM);

    // 1) conversions + rope table (single launch)
    split_all<<<SPLIT_BLOCKS, 256>>>(x, q_a, kv_a, q_b, kv_b, o_w,
                                     x_hi, x_lo, qk_h, qb_h, kvb_h, ow_h, rope);

    // 2) merged x-GEMM: XC = x @ [q_a; kv_a]^T (fp32 only for k_rot cols >=2048)
    gemm_one<<<dim3(17, 32), 256, GEMM_SMEM>>>(x_hi, x_lo, EMB, qk_h,
                                               XC, XC_hi, XC_lo, NXC, EMB, NXC, 2048);

    // 3) grouped: Q = Xq @ q_b^T  +  KVB = ckv512 @ kv_b^T
    gemm_two<<<dim3(16 + 24, 32), 256, GEMM_SMEM>>>(
        XC_hi, XC_lo, NXC, qb_h, Q, 2048, QRANK, 2048,
        XC_hi + QRANK, XC_lo + QRANK, NXC, kvb_h, KVB, 3072, KVRANK, 3072,
        16);

    // 4) fused repack (pair-vectorized)
    repack_all<<<2 * MROWS + 1024, 1024>>>(Q, KVB, XC, rope,
                                           Qb_hi, Qb_lo, Kb_h, Vt_h);

    // 5) attention (R10 config: occ 2)
    flash_mma<<<dim3(SLEN / 64, BHN), 128, FLASH_SMEM>>>(
        Qb_hi, Qb_lo, Kb_h, Vt_h, O_hi, O_lo);

    // 6) out = O @ o_w^T
    gemm_one<<<dim3(16, 32), 256, GEMM_SMEM>>>(O_hi, O_lo, EMB, ow_h,
                                               out, nullptr, nullptr,
                                               EMB, NHEAD * V_D, EMB, 0);
}

// round 13
// speedup vs baseline: 1.1065x; 1.0045x over previous
#include <cuda_runtime.h>
#include <cuda_fp16.h>
#include <math.h>
#include <stdint.h>

// ---------------------------------------------------------------------------
// Problem constants
// ---------------------------------------------------------------------------
#define BATCH   2
#define SLEN    2048
#define EMB     2048
#define NHEAD   16
#define QRANK   1536
#define KVRANK  512
#define QK_D    128
#define V_D     128
#define MROWS   (BATCH * SLEN)        // 4096
#define BHN     (BATCH * NHEAD)       // 32
#define NXC     (QRANK + 576)         // 2112

// ------------------------- fp32 scratch -----------------------------------
__device__ float  g_XC [(size_t)MROWS * NXC];           // only cols >=2048 written/read
__device__ float  g_Q  [(size_t)MROWS * (NHEAD * QK_D)];
__device__ float2 g_rope[SLEN * 32];                    // (cos, sin)

// ------------------------- fp16 buffers -----------------------------------
__device__ __half g_x_hi   [(size_t)MROWS * EMB];
__device__ __half g_x_lo   [(size_t)MROWS * EMB];
__device__ __half g_qakva_h[(size_t)NXC * EMB];
__device__ __half g_qb_h   [(size_t)(NHEAD * QK_D) * QRANK];
__device__ __half g_kvb_h  [(size_t)3072 * KVRANK];
__device__ __half g_ow_h   [(size_t)EMB * (NHEAD * V_D)];
__device__ __half g_XC_hi  [(size_t)MROWS * NXC];
__device__ __half g_XC_lo  [(size_t)MROWS * NXC];
__device__ __half g_KVBh   [(size_t)MROWS * 3072];      // fp16 KVB (B-side precision)
__device__ __half g_Qb_hi  [(size_t)BHN * SLEN * QK_D];
__device__ __half g_Qb_lo  [(size_t)BHN * SLEN * QK_D];
__device__ __half g_Kb_h   [(size_t)BHN * SLEN * QK_D];
__device__ __half g_Vt_h   [(size_t)BHN * V_D * SLEN];
__device__ __half g_O_hi   [(size_t)MROWS * (NHEAD * V_D)];
__device__ __half g_O_lo   [(size_t)MROWS * (NHEAD * V_D)];

// ---------------------------------------------------------------------------
// PTX helpers
// ---------------------------------------------------------------------------
__device__ __forceinline__ uint32_t cvta_s(const void* p) {
    return (uint32_t)__cvta_generic_to_shared(p);
}
__device__ __forceinline__ void cp16(uint32_t dst, const void* src) {
    asm volatile("cp.async.cg.shared.global [%0], [%1], 16;"
                 :: "r"(dst), "l"(src) : "memory");
}
__device__ __forceinline__ void cp16_pred(uint32_t dst, const void* src, bool valid) {
    const int sz = valid ? 16 : 0;
    asm volatile("cp.async.cg.shared.global [%0], [%1], 16, %2;"
                 :: "r"(dst), "l"(src), "r"(sz) : "memory");
}
__device__ __forceinline__ void cp_commit() {
    asm volatile("cp.async.commit_group;" ::: "memory");
}
__device__ __forceinline__ void ldm_x4(uint32_t* r, uint32_t addr) {
    asm volatile("ldmatrix.sync.aligned.m8n8.x4.shared.b16 {%0,%1,%2,%3}, [%4];"
                 : "=r"(r[0]), "=r"(r[1]), "=r"(r[2]), "=r"(r[3]) : "r"(addr));
}
__device__ __forceinline__ void ldm_x2(uint32_t& r0, uint32_t& r1, uint32_t addr) {
    asm volatile("ldmatrix.sync.aligned.m8n8.x2.shared.b16 {%0,%1}, [%2];"
                 : "=r"(r0), "=r"(r1) : "r"(addr));
}
__device__ __forceinline__ void mma_f16(float* c, const uint32_t* a,
                                        const uint32_t* b) {
    asm volatile(
        "mma.sync.aligned.m16n8k16.row.col.f32.f16.f16.f32 "
        "{%0,%1,%2,%3}, {%4,%5,%6,%7}, {%8,%9}, {%0,%1,%2,%3};"
        : "+f"(c[0]), "+f"(c[1]), "+f"(c[2]), "+f"(c[3])
        : "r"(a[0]), "r"(a[1]), "r"(a[2]), "r"(a[3]), "r"(b[0]), "r"(b[1]));
}
__device__ __forceinline__ uint32_t pack_h2(float lo, float hi) {
    uint32_t r;
    asm("cvt.rn.f16x2.f32 %0, %1, %2;" : "=r"(r) : "f"(hi), "f"(lo));
    return r;
}
__device__ __forceinline__ float h_res(float v) {
    return v - __half2float(__float2half_rn(v));
}

// ---------------------------------------------------------------------------
// HMMA 2-term fp16 GEMM (NT). Epilogue modes:
//   C   != null            : fp32 store for cols >= c0
//   Chi != null, Clo !=null : fp16 hi/lo pair store
//   Chi != null, Clo ==null : fp16 hi-only (rounded) store
// ---------------------------------------------------------------------------
#define LDP 40
#define TILE_B (128 * LDP * 2)
#define STAGE_B (3 * TILE_B)
#define GEMM_SMEM (2 * STAGE_B)

__device__ __forceinline__ void gload_stage(
    uint32_t sb, const __half* Ahi, const __half* Alo, int lda,
    const __half* Bh, int bm, int bn, int k0, int K, int N, int tid)
{
    #pragma unroll
    for (int idx = tid; idx < 512; idx += 256) {
        const int r = idx >> 2, c = idx & 3;
        const uint32_t so = (uint32_t)(r * LDP * 2 + c * 16);
        const size_t ga = (size_t)(bm + r) * lda + k0 + c * 8;
        cp16(sb + 0 * TILE_B + so, Ahi + ga);
        cp16(sb + 1 * TILE_B + so, Alo + ga);
        const bool v = (bn + r) < N;
        const size_t gb = v ? ((size_t)(bn + r) * K + k0 + c * 8) : 0;
        cp16_pred(sb + 2 * TILE_B + so, Bh + gb, v);
    }
}

__device__ __forceinline__ void gemm_body(
    uint32_t sbase,
    const __half* __restrict__ Ahi, const __half* __restrict__ Alo, int lda,
    const __half* __restrict__ Bh,
    float* __restrict__ C, __half* __restrict__ Chi, __half* __restrict__ Clo,
    int N, int K, int ldc, int bm, int bn, int c0)
{
    const int tid  = threadIdx.x;
    const int wid  = tid >> 5;
    const int lane = tid & 31;
    const int warp_m = (wid >> 2) * 64;
    const int warp_n = (wid & 3) * 32;
    const int nk = K / 32;

    float acc[4][4][4];
    #pragma unroll
    for (int i = 0; i < 4; ++i)
        #pragma unroll
        for (int j = 0; j < 4; ++j)
            #pragma unroll
            for (int q = 0; q < 4; ++q) acc[i][j][q] = 0.f;

    gload_stage(sbase, Ahi, Alo, lda, Bh, bm, bn, 0, K, N, tid);
    cp_commit();

    const int a_row = lane & 15;
    const int a_coff = (lane >> 4) << 3;
    const int b_row = lane & 7;
    const int b_coff = ((lane >> 3) & 1) << 3;

    for (int i = 0; i < nk; ++i) {
        if (i + 1 < nk) {
            gload_stage(sbase + ((i + 1) & 1) * STAGE_B, Ahi, Alo, lda, Bh,
                        bm, bn, (i + 1) * 32, K, N, tid);
            cp_commit();
            asm volatile("cp.async.wait_group 1;" ::: "memory");
        } else {
            asm volatile("cp.async.wait_group 0;" ::: "memory");
        }
        __syncthreads();

        const uint32_t sb = sbase + (i & 1) * STAGE_B;
        #pragma unroll
        for (int kc = 0; kc < 2; ++kc) {
            const int kel = kc * 16;
            uint32_t ah[4][4], al[4][4];
            #pragma unroll
            for (int mi = 0; mi < 4; ++mi) {
                const uint32_t ao = (uint32_t)((warp_m + mi * 16 + a_row) * LDP
                                               + kel + a_coff) * 2;
                ldm_x4(ah[mi], sb + ao);
                ldm_x4(al[mi], sb + TILE_B + ao);
            }
            #pragma unroll
            for (int ni = 0; ni < 4; ++ni) {
                const uint32_t bo = (uint32_t)((warp_n + ni * 8 + b_row) * LDP
                                               + kel + b_coff) * 2;
                uint32_t bh[2];
                ldm_x2(bh[0], bh[1], sb + 2 * TILE_B + bo);
                #pragma unroll
                for (int mi = 0; mi < 4; ++mi) {
                    mma_f16(acc[mi][ni], ah[mi], bh);
                    mma_f16(acc[mi][ni], al[mi], bh);
                }
            }
        }
        __syncthreads();
    }

    const int er = lane >> 2;
    const int ec = (lane & 3) * 2;
    #pragma unroll
    for (int mi = 0; mi < 4; ++mi) {
        #pragma unroll
        for (int ni = 0; ni < 4; ++ni) {
            const int col = bn + warp_n + ni * 8 + ec;
            if (col < N) {
                const int r0 = bm + warp_m + mi * 16 + er;
                const float a0 = acc[mi][ni][0], a1 = acc[mi][ni][1];
                const float a2 = acc[mi][ni][2], a3 = acc[mi][ni][3];
                if (C && col >= c0) {
                    *(float2*)(C + (size_t)r0 * ldc + col) = make_float2(a0, a1);
                    *(float2*)(C + (size_t)(r0 + 8) * ldc + col) = make_float2(a2, a3);
                }
                if (Chi) {
                    *(uint32_t*)(Chi + (size_t)r0 * ldc + col) = pack_h2(a0, a1);
                    *(uint32_t*)(Chi + (size_t)(r0 + 8) * ldc + col) = pack_h2(a2, a3);
                    if (Clo) {
                        *(uint32_t*)(Clo + (size_t)r0 * ldc + col) =
                            pack_h2(h_res(a0), h_res(a1));
                        *(uint32_t*)(Clo + (size_t)(r0 + 8) * ldc + col) =
                            pack_h2(h_res(a2), h_res(a3));
                    }
                }
            }
        }
    }
}

__global__ __launch_bounds__(256, 2)
void gemm_one(const __half* __restrict__ Ahi, const __half* __restrict__ Alo,
              int lda, const __half* __restrict__ Bh,
              float* __restrict__ C, __half* __restrict__ Chi,
              __half* __restrict__ Clo, int N, int K, int ldc, int c0)
{
    extern __shared__ char smraw[];
    gemm_body(cvta_s(smraw), Ahi, Alo, lda, Bh, C, Chi, Clo,
              N, K, ldc, blockIdx.y * 128, blockIdx.x * 128, c0);
}

__global__ __launch_bounds__(256, 2)
void gemm_two(const __half* A1h, const __half* A1l, int lda1, const __half* B1,
              float* C1, int N1, int K1, int ldc1,
              const __half* A2h, const __half* A2l, int lda2, const __half* B2,
              __half* C2h, int N2, int K2, int ldc2, int bx_split)
{
    extern __shared__ char smraw[];
    const uint32_t sb = cvta_s(smraw);
    if ((int)blockIdx.x < bx_split)
        gemm_body(sb, A1h, A1l, lda1, B1, C1, nullptr, nullptr,
                  N1, K1, ldc1, blockIdx.y * 128, blockIdx.x * 128, 0);
    else
        gemm_body(sb, A2h, A2l, lda2, B2, nullptr, C2h, nullptr,
                  N2, K2, ldc2, blockIdx.y * 128, (blockIdx.x - bx_split) * 128, 0);
}

// ---------------------------------------------------------------------------
// Grouped fp32 -> fp16 conversion + rope table — identical to R12
// ---------------------------------------------------------------------------
union HV4 { __half h[4]; ushort4 u; };

#define NV4_X   (MROWS * EMB / 4)
#define NV4_QA  (QRANK * EMB / 4)
#define NV4_KVA (576 * EMB / 4)
#define NV4_QB  ((NHEAD * QK_D) * QRANK / 4)
#define NV4_KVB (3072 * KVRANK / 4)
#define NV4_OW  (EMB * (NHEAD * V_D) / 4)
#define C1_ (NV4_X)
#define C2_ (C1_ + NV4_QA)
#define C3_ (C2_ + NV4_KVA)
#define C4_ (C3_ + NV4_QB)
#define C5_ (C4_ + NV4_KVB)
#define C6_ (C5_ + NV4_OW)
#define C7_ (C6_ + SLEN * 32)
#define SPLIT_BLOCKS ((C7_ + 255) / 256)

__global__ void split_all(const float* __restrict__ x,  const float* __restrict__ qa,
                          const float* __restrict__ kva, const float* __restrict__ qb,
                          const float* __restrict__ kvb, const float* __restrict__ ow,
                          __half* __restrict__ xh,  __half* __restrict__ xl,
                          __half* __restrict__ qkh, __half* __restrict__ qbh,
                          __half* __restrict__ kvbh, __half* __restrict__ owh,
                          float2* __restrict__ rope)
{
    const int i = blockIdx.x * blockDim.x + threadIdx.x;
    if (i >= C7_) return;

    if (i >= C6_) {
        const int e = i - C6_;
        const int s = e >> 5, t = e & 31;
        const float theta = powf(10000.f, -((float)(2 * t)) / 64.f);
        float sn, cs;
        sincosf((float)s * theta, &sn, &cs);
        rope[e] = make_float2(cs, sn);
        return;
    }

    const float* src; __half* hi; int o; bool do_lo = false;
    if (i < C1_)      { src = x;   hi = xh;   o = i;       do_lo = true; }
    else if (i < C2_) { src = qa;  hi = qkh;  o = i - C1_; }
    else if (i < C3_) { src = kva; hi = qkh + (size_t)QRANK * EMB; o = i - C2_; }
    else if (i < C4_) { src = qb;  hi = qbh;  o = i - C3_; }
    else if (i < C5_) { src = kvb; hi = kvbh; o = i - C4_; }
    else              { src = ow;  hi = owh;  o = i - C5_; }

    const float4 v = ((const float4*)src)[o];
    const float vv[4] = { v.x, v.y, v.z, v.w };
    HV4 H;
    #pragma unroll
    for (int j = 0; j < 4; ++j) H.h[j] = __float2half_rn(vv[j]);
    ((ushort4*)hi)[o] = H.u;
    if (do_lo) {
        HV4 L;
        #pragma unroll
        for (int j = 0; j < 4; ++j)
            L.h[j] = __float2half_rn(vv[j] - __half2float(H.h[j]));
        ((ushort4*)xl)[o] = L.u;
    }
}

// ---------------------------------------------------------------------------
// Fused repack: Q (fp32->hi/lo, rope), K (fp16 copy + rope from XC),
// V transpose (fp16 raw-bit repack). KVB is now fp16.
// ---------------------------------------------------------------------------
__global__ __launch_bounds__(1024)
void repack_all(const float* __restrict__ Q, const __half* __restrict__ KVBh,
                const float* __restrict__ XC, const float2* __restrict__ rope,
                __half* __restrict__ Qh, __half* __restrict__ Ql,
                __half* __restrict__ Kh, __half* __restrict__ Vh)
{
    __shared__ __half tile[64][136];
    const int bb = blockIdx.x;
    const int tid = threadIdx.x;

    if (bb < 2 * MROWS) {
        const bool is_q = bb < MROWS;
        const int bs = is_q ? bb : bb - MROWS;
        const int b  = bs >> 11;
        const int s  = bs & 2047;
        const int h  = tid >> 6;          // 0..15
        const int t  = tid & 63;          // pair index
        const size_t dst = ((size_t)(b * NHEAD + h) * SLEN + s) * QK_D + 2 * t;

        if (is_q) {
            float v0, v1;
            const float* src = Q + (size_t)bs * (NHEAD * QK_D) + h * QK_D;
            if (t < 32) {
                const float2 p = *(const float2*)(src + 2 * t);
                v0 = p.x; v1 = p.y;
            } else {
                const int tr = t - 32;
                const float2 cs = rope[s * 32 + tr];
                const float2 p = *(const float2*)(src + 64 + 2 * tr);
                v0 = p.x * cs.x - p.y * cs.y;
                v1 = p.y * cs.x + p.x * cs.y;
            }
            *(uint32_t*)(Qh + dst) = pack_h2(v0, v1);
            *(uint32_t*)(Ql + dst) = pack_h2(h_res(v0), h_res(v1));
        } else {
            if (t < 32) {
                // K-pass: direct fp16 copy
                *(uint32_t*)(Kh + dst) =
                    *(const uint32_t*)(KVBh + (size_t)bs * 3072 + h * 192 + 2 * t);
            } else {
                const int tr = t - 32;
                const float2 cs = rope[s * 32 + tr];
                const float* kr = XC + (size_t)bs * NXC + 2048;
                const float2 p = *(const float2*)(kr + 2 * tr);
                const float v0 = p.x * cs.x - p.y * cs.y;
                const float v1 = p.y * cs.x + p.x * cs.y;
                *(uint32_t*)(Kh + dst) = pack_h2(v0, v1);
            }
        }
    } else {
        // V transpose: KVBh[bs][h*192+64+d] -> Vt[bh][d][s], raw fp16 bits
        const int idx = bb - 2 * MROWS;
        const int bh  = idx >> 5;
        const int s0  = (idx & 31) * 64;
        const int b   = bh >> 4;
        const int h   = bh & 15;

        {
            const int r = tid >> 4;             // 0..63
            const int c = (tid & 15) * 8;       // 0..120
            const uint4 v = *(const uint4*)(KVBh + (size_t)(b * SLEN + s0 + r) * 3072
                                            + h * 192 + 64 + c);
            *(uint4*)&tile[r][c] = v;
        }
        __syncthreads();

        const int d = tid >> 3;                 // 0..127
        const int chunk = tid & 7;              // 0..7
        const size_t obase = ((size_t)bh * 128 + d) * SLEN + s0 + chunk * 8;
        #pragma unroll
        for (int j = 0; j < 8; j += 2) {
            const uint32_t w = (uint32_t)__half_as_ushort(tile[chunk * 8 + j][d])
                             | ((uint32_t)__half_as_ushort(tile[chunk * 8 + j + 1][d]) << 16);
            *(uint32_t*)(Vh + obase + j) = w;
        }
    }
}

// ---------------------------------------------------------------------------
// Flash attention — identical to R12 (128 thr, 64-row Q tiles, occ 2)
// ---------------------------------------------------------------------------
#define QLDE 136
#define VLDE 72
#define OFF_QH 0
#define OFF_QL 17408
#define OFF_STG 34816
#define STG_SZ 35840
#define SOFF_KH 0
#define SOFF_VH 17408
#define FLASH_SMEM (OFF_STG + 2 * STG_SZ)   // 106496

__device__ __forceinline__ void fa_load_kv(
    uint32_t base, const __half* Kh, const __half* Vh, int bh, int kt, int tid)
{
    const size_t gk = ((size_t)bh * SLEN + kt * 64) * QK_D;
    #pragma unroll
    for (int i = tid; i < 1024; i += 128) {
        const int r = i >> 4, c = (i & 15) * 8;
        cp16(base + SOFF_KH + (uint32_t)(r * QLDE + c) * 2,
             Kh + gk + (size_t)r * QK_D + c);
    }
    const size_t gv = (size_t)bh * V_D * SLEN + kt * 64;
    #pragma unroll
    for (int i = tid; i < 1024; i += 128) {
        const int r = i >> 3, c = (i & 7) * 8;
        cp16(base + SOFF_VH + (uint32_t)(r * VLDE + c) * 2,
             Vh + gv + (size_t)r * SLEN + c);
    }
}

__global__ __launch_bounds__(128, 2)
void flash_mma(const __half* __restrict__ Qh, const __half* __restrict__ Ql,
               const __half* __restrict__ Kh, const __half* __restrict__ Vh,
               __half* __restrict__ Ohi, __half* __restrict__ Olo)
{
    extern __shared__ char smraw[];
    const uint32_t sb0 = cvta_s(smraw);

    const int tid  = threadIdx.x;
    const int wid  = tid >> 5;
    const int lane = tid & 31;
    const int bh = blockIdx.y;
    const int b  = bh >> 4;
    const int h  = bh & 15;
    const int q0 = blockIdx.x * 64;
    const int r_base = wid * 16;

    const size_t gq = ((size_t)bh * SLEN + q0) * QK_D;
    #pragma unroll
    for (int i = tid; i < 1024; i += 128) {
        const int r = i >> 4, c = (i & 15) * 8;
        const uint32_t so = (uint32_t)(r * QLDE + c) * 2;
        cp16(sb0 + OFF_QH + so, Qh + gq + (size_t)r * QK_D + c);
        cp16(sb0 + OFF_QL + so, Ql + gq + (size_t)r * QK_D + c);
    }
    fa_load_kv(sb0 + OFF_STG, Kh, Vh, bh, 0, tid);
    cp_commit();
    asm volatile("cp.async.wait_group 0;" ::: "memory");
    __syncthreads();

    uint32_t qfh[8][4], qfl[8][4];
    {
        const int ar = lane & 15;
        const int ac = ((lane >> 4) & 1) * 8;
        #pragma unroll
        for (int kf = 0; kf < 8; ++kf) {
            const uint32_t off = (uint32_t)((r_base + ar) * QLDE + kf * 16 + ac) * 2;
            ldm_x4(qfh[kf], sb0 + OFF_QH + off);
            ldm_x4(qfl[kf], sb0 + OFF_QL + off);
        }
    }

    float Oa[16][4];
    #pragma unroll
    for (int i = 0; i < 16; ++i)
        #pragma unroll
        for (int j = 0; j < 4; ++j) Oa[i][j] = 0.f;
    float m0 = -INFINITY, m1 = -INFINITY, l0 = 0.f, l1 = 0.f;

    const int krow = lane & 7;
    const int kcol = ((lane >> 3) & 3) * 8;

    for (int kt = 0; kt < SLEN / 64; ++kt) {
        if (kt + 1 < SLEN / 64) {
            fa_load_kv(sb0 + OFF_STG + ((kt + 1) & 1) * STG_SZ, Kh, Vh, bh, kt + 1, tid);
            cp_commit();
            asm volatile("cp.async.wait_group 1;" ::: "memory");
        } else {
            asm volatile("cp.async.wait_group 0;" ::: "memory");
        }
        __syncthreads();

        const uint32_t sk = sb0 + OFF_STG + (kt & 1) * STG_SZ;

        float S[8][4];
        #pragma unroll
        for (int i = 0; i < 8; ++i)
            #pragma unroll
            for (int j = 0; j < 4; ++j) S[i][j] = 0.f;

        #pragma unroll
        for (int nb = 0; nb < 8; ++nb) {
            #pragma unroll
            for (int kfp = 0; kfp < 4; ++kfp) {
                const uint32_t ko = (uint32_t)((nb * 8 + krow) * QLDE
                                               + kfp * 32 + kcol) * 2;
                uint32_t kfh[4];
                ldm_x4(kfh, sk + SOFF_KH + ko);
                mma_f16(S[nb], qfh[2 * kfp],     kfh);
                mma_f16(S[nb], qfh[2 * kfp + 1], kfh + 2);
                mma_f16(S[nb], qfl[2 * kfp],     kfh);
                mma_f16(S[nb], qfl[2 * kfp + 1], kfh + 2);
            }
        }

        float mx0 = -INFINITY, mx1 = -INFINITY;
        #pragma unroll
        for (int nb = 0; nb < 8; ++nb) {
            mx0 = fmaxf(mx0, fmaxf(S[nb][0], S[nb][1]));
            mx1 = fmaxf(mx1, fmaxf(S[nb][2], S[nb][3]));
        }
        mx0 = fmaxf(mx0, __shfl_xor_sync(0xffffffffu, mx0, 1));
        mx0 = fmaxf(mx0, __shfl_xor_sync(0xffffffffu, mx0, 2));
        mx1 = fmaxf(mx1, __shfl_xor_sync(0xffffffffu, mx1, 1));
        mx1 = fmaxf(mx1, __shfl_xor_sync(0xffffffffu, mx1, 2));

        const float mn0 = fmaxf(m0, mx0);
        const float mn1 = fmaxf(m1, mx1);
        const float f0 = __expf(m0 - mn0);
        const float f1 = __expf(m1 - mn1);
        m0 = mn0; m1 = mn1;

        float rs0 = 0.f, rs1 = 0.f;
        #pragma unroll
        for (int nb = 0; nb < 8; ++nb) {
            S[nb][0] = __expf(S[nb][0] - mn0);
            S[nb][1] = __expf(S[nb][1] - mn0);
            S[nb][2] = __expf(S[nb][2] - mn1);
            S[nb][3] = __expf(S[nb][3] - mn1);
            rs0 += S[nb][0] + S[nb][1];
            rs1 += S[nb][2] + S[nb][3];
        }
        rs0 += __shfl_xor_sync(0xffffffffu, rs0, 1);
        rs0 += __shfl_xor_sync(0xffffffffu, rs0, 2);
        rs1 += __shfl_xor_sync(0xffffffffu, rs1, 1);
        rs1 += __shfl_xor_sync(0xffffffffu, rs1, 2);
        l0 = l0 * f0 + rs0;
        l1 = l1 * f1 + rs1;

        #pragma unroll
        for (int i = 0; i < 16; ++i) {
            Oa[i][0] *= f0; Oa[i][1] *= f0;
            Oa[i][2] *= f1; Oa[i][3] *= f1;
        }

        uint32_t ph[4][4], pl[4][4];
        #pragma unroll
        for (int kf2 = 0; kf2 < 4; ++kf2) {
            const float* s0p = S[2 * kf2];
            const float* s1p = S[2 * kf2 + 1];
            ph[kf2][0] = pack_h2(s0p[0], s0p[1]);
            ph[kf2][1] = pack_h2(s0p[2], s0p[3]);
            ph[kf2][2] = pack_h2(s1p[0], s1p[1]);
            ph[kf2][3] = pack_h2(s1p[2], s1p[3]);
            pl[kf2][0] = pack_h2(h_res(s0p[0]), h_res(s0p[1]));
            pl[kf2][1] = pack_h2(h_res(s0p[2]), h_res(s0p[3]));
            pl[kf2][2] = pack_h2(h_res(s1p[0]), h_res(s1p[1]));
            pl[kf2][3] = pack_h2(h_res(s1p[2]), h_res(s1p[3]));
        }

        #pragma unroll
        for (int nb2 = 0; nb2 < 16; ++nb2) {
            #pragma unroll
            for (int kfp2 = 0; kfp2 < 2; ++kfp2) {
                const uint32_t vo = (uint32_t)((nb2 * 8 + krow) * VLDE
                                               + kfp2 * 32 + kcol) * 2;
                uint32_t vfh[4];
                ldm_x4(vfh, sk + SOFF_VH + vo);
                mma_f16(Oa[nb2], ph[2 * kfp2],     vfh);
                mma_f16(Oa[nb2], ph[2 * kfp2 + 1], vfh + 2);
                mma_f16(Oa[nb2], pl[2 * kfp2],     vfh);
                mma_f16(Oa[nb2], pl[2 * kfp2 + 1], vfh + 2);
            }
        }
        __syncthreads();
    }

    const float inv0 = 1.f / l0;
    const float inv1 = 1.f / l1;
    const int er = lane >> 2;
    const int ec = (lane & 3) * 2;
    const size_t row0 = (size_t)(b * SLEN + q0 + r_base + er) * (NHEAD * V_D) + h * V_D;
    const size_t row1 = row0 + (size_t)8 * (NHEAD * V_D);
    #pragma unroll
    for (int nb2 = 0; nb2 < 16; ++nb2) {
        const int col = nb2 * 8 + ec;
        const float a0 = Oa[nb2][0] * inv0, a1 = Oa[nb2][1] * inv0;
        const float a2 = Oa[nb2][2] * inv1, a3 = Oa[nb2][3] * inv1;
        *(uint32_t*)(Ohi + row0 + col) = pack_h2(a0, a1);
        *(uint32_t*)(Olo + row0 + col) = pack_h2(h_res(a0), h_res(a1));
        *(uint32_t*)(Ohi + row1 + col) = pack_h2(a2, a3);
        *(uint32_t*)(Olo + row1 + col) = pack_h2(h_res(a2), h_res(a3));
    }
}

// ---------------------------------------------------------------------------
extern "C" void kernel_launch(void* const* d_in, const int* in_sizes, int n_in,
                              void* d_out, int out_size)
{
    const float* x    = (const float*)d_in[0];
    const float* q_a  = (const float*)d_in[1];
    const float* q_b  = (const float*)d_in[2];
    const float* kv_a = (const float*)d_in[3];
    const float* kv_b = (const float*)d_in[4];
    const float* o_w  = (const float*)d_in[5];
    float* out = (float*)d_out;

    float *XC, *Q;
    float2* rope;
    cudaGetSymbolAddress((void**)&XC,   g_XC);
    cudaGetSymbolAddress((void**)&Q,    g_Q);
    cudaGetSymbolAddress((void**)&rope, g_rope);

    __half *x_hi, *x_lo, *qk_h, *qb_h, *kvb_h, *ow_h, *XC_hi, *XC_lo, *KVBh;
    __half *Qb_hi, *Qb_lo, *Kb_h, *Vt_h, *O_hi, *O_lo;
    cudaGetSymbolAddress((void**)&x_hi,  g_x_hi);
    cudaGetSymbolAddress((void**)&x_lo,  g_x_lo);
    cudaGetSymbolAddress((void**)&qk_h,  g_qakva_h);
    cudaGetSymbolAddress((void**)&qb_h,  g_qb_h);
    cudaGetSymbolAddress((void**)&kvb_h, g_kvb_h);
    cudaGetSymbolAddress((void**)&ow_h,  g_ow_h);
    cudaGetSymbolAddress((void**)&XC_hi, g_XC_hi);
    cudaGetSymbolAddress((void**)&XC_lo, g_XC_lo);
    cudaGetSymbolAddress((void**)&KVBh,  g_KVBh);
    cudaGetSymbolAddress((void**)&Qb_hi, g_Qb_hi);
    cudaGetSymbolAddress((void**)&Qb_lo, g_Qb_lo);
    cudaGetSymbolAddress((void**)&Kb_h,  g_Kb_h);
    cudaGetSymbolAddress((void**)&Vt_h,  g_Vt_h);
    cudaGetSymbolAddress((void**)&O_hi,  g_O_hi);
    cudaGetSymbolAddress((void**)&O_lo,  g_O_lo);

    cudaFuncSetAttribute(gemm_one, cudaFuncAttributeMaxDynamicSharedMemorySize,
                         GEMM_SMEM);
    cudaFuncSetAttribute(gemm_two, cudaFuncAttributeMaxDynamicSharedMemorySize,
                         GEMM_SMEM);
    cudaFuncSetAttribute(flash_mma, cudaFuncAttributeMaxDynamicSharedMemorySize,
                         FLASH_SMEM);

    // 1) conversions + rope table (single launch)
    split_all<<<SPLIT_BLOCKS, 256>>>(x, q_a, kv_a, q_b, kv_b, o_w,
                                     x_hi, x_lo, qk_h, qb_h, kvb_h, ow_h, rope);

    // 2) merged x-GEMM: XC = x @ [q_a; kv_a]^T (fp32 only for k_rot cols >=2048)
    gemm_one<<<dim3(17, 32), 256, GEMM_SMEM>>>(x_hi, x_lo, EMB, qk_h,
                                               XC, XC_hi, XC_lo, NXC, EMB, NXC, 2048);

    // 3) grouped: Q = Xq @ q_b^T (fp32)  +  KVB = ckv512 @ kv_b^T (fp16 hi-only)
    gemm_two<<<dim3(16 + 24, 32), 256, GEMM_SMEM>>>(
        XC_hi, XC_lo, NXC, qb_h, Q, 2048, QRANK, 2048,
        XC_hi + QRANK, XC_lo + QRANK, NXC, kvb_h, KVBh, 3072, KVRANK, 3072,
        16);

    // 4) fused repack (KVB now fp16: K copy, V raw-bit transpose)
    repack_all<<<2 * MROWS + 1024, 1024>>>(Q, KVBh, XC, rope,
                                           Qb_hi, Qb_lo, Kb_h, Vt_h);

    // 5) attention (occ 2)
    flash_mma<<<dim3(SLEN / 64, BHN), 128, FLASH_SMEM>>>(
        Qb_hi, Qb_lo, Kb_h, Vt_h, O_hi, O_lo);

    // 6) out = O @ o_w^T
    gemm_one<<<dim3(16, 32), 256, GEMM_SMEM>>>(O_hi, O_lo, EMB, ow_h,
                                               out, nullptr, nullptr,
                                               EMB, NHEAD * V_D, EMB, 0);
}

// round 14
// speedup vs baseline: 1.1095x; 1.0027x over previous
#include <cuda_runtime.h>
#include <cuda_fp16.h>
#include <math.h>
#include <stdint.h>

// ---------------------------------------------------------------------------
// Problem constants
// ---------------------------------------------------------------------------
#define BATCH   2
#define SLEN    2048
#define EMB     2048
#define NHEAD   16
#define QRANK   1536
#define KVRANK  512
#define QK_D    128
#define V_D     128
#define MROWS   (BATCH * SLEN)        // 4096
#define BHN     (BATCH * NHEAD)       // 32
#define NXC     (QRANK + 576)         // 2112

// ------------------------- fp32 scratch -----------------------------------
__device__ float  g_XC [(size_t)MROWS * NXC];           // only cols >=2048 written/read
__device__ float2 g_rope[SLEN * 32];                    // (cos, sin)

// ------------------------- fp16 buffers -----------------------------------
__device__ __half g_x_hi   [(size_t)MROWS * EMB];
__device__ __half g_x_lo   [(size_t)MROWS * EMB];
__device__ __half g_qakva_h[(size_t)NXC * EMB];
__device__ __half g_qb_h   [(size_t)(NHEAD * QK_D) * QRANK];
__device__ __half g_kvb_h  [(size_t)3072 * KVRANK];
__device__ __half g_ow_h   [(size_t)EMB * (NHEAD * V_D)];
__device__ __half g_XC_hi  [(size_t)MROWS * NXC];
__device__ __half g_XC_lo  [(size_t)MROWS * NXC];
__device__ __half g_KVBh   [(size_t)MROWS * 3072];
// Qb kept in natural [bs][h*128+d] layout (roped, hi/lo)
__device__ __half g_Qb_hi  [(size_t)MROWS * (NHEAD * QK_D)];
__device__ __half g_Qb_lo  [(size_t)MROWS * (NHEAD * QK_D)];
__device__ __half g_Kb_h   [(size_t)BHN * SLEN * QK_D];
__device__ __half g_Vt_h   [(size_t)BHN * V_D * SLEN];
__device__ __half g_O_hi   [(size_t)MROWS * (NHEAD * V_D)];
__device__ __half g_O_lo   [(size_t)MROWS * (NHEAD * V_D)];

// ---------------------------------------------------------------------------
// PTX helpers
// ---------------------------------------------------------------------------
__device__ __forceinline__ uint32_t cvta_s(const void* p) {
    return (uint32_t)__cvta_generic_to_shared(p);
}
__device__ __forceinline__ void cp16(uint32_t dst, const void* src) {
    asm volatile("cp.async.cg.shared.global [%0], [%1], 16;"
                 :: "r"(dst), "l"(src) : "memory");
}
__device__ __forceinline__ void cp16_pred(uint32_t dst, const void* src, bool valid) {
    const int sz = valid ? 16 : 0;
    asm volatile("cp.async.cg.shared.global [%0], [%1], 16, %2;"
                 :: "r"(dst), "l"(src), "r"(sz) : "memory");
}
__device__ __forceinline__ void cp_commit() {
    asm volatile("cp.async.commit_group;" ::: "memory");
}
__device__ __forceinline__ void ldm_x4(uint32_t* r, uint32_t addr) {
    asm volatile("ldmatrix.sync.aligned.m8n8.x4.shared.b16 {%0,%1,%2,%3}, [%4];"
                 : "=r"(r[0]), "=r"(r[1]), "=r"(r[2]), "=r"(r[3]) : "r"(addr));
}
__device__ __forceinline__ void ldm_x2(uint32_t& r0, uint32_t& r1, uint32_t addr) {
    asm volatile("ldmatrix.sync.aligned.m8n8.x2.shared.b16 {%0,%1}, [%2];"
                 : "=r"(r0), "=r"(r1) : "r"(addr));
}
__device__ __forceinline__ void mma_f16(float* c, const uint32_t* a,
                                        const uint32_t* b) {
    asm volatile(
        "mma.sync.aligned.m16n8k16.row.col.f32.f16.f16.f32 "
        "{%0,%1,%2,%3}, {%4,%5,%6,%7}, {%8,%9}, {%0,%1,%2,%3};"
        : "+f"(c[0]), "+f"(c[1]), "+f"(c[2]), "+f"(c[3])
        : "r"(a[0]), "r"(a[1]), "r"(a[2]), "r"(a[3]), "r"(b[0]), "r"(b[1]));
}
__device__ __forceinline__ uint32_t pack_h2(float lo, float hi) {
    uint32_t r;
    asm("cvt.rn.f16x2.f32 %0, %1, %2;" : "=r"(r) : "f"(hi), "f"(lo));
    return r;
}
__device__ __forceinline__ float h_res(float v) {
    return v - __half2float(__float2half_rn(v));
}

// ---------------------------------------------------------------------------
// HMMA 2-term fp16 GEMM (NT). Epilogue modes:
//   QROPE=false: C(fp32, cols>=c0) and/or Chi[/Clo] fp16 stores
//   QROPE=true : rope applied in-register, Chi/Clo hi+lo stores (Q path)
// ---------------------------------------------------------------------------
#define LDP 40
#define TILE_B (128 * LDP * 2)
#define STAGE_B (3 * TILE_B)
#define GEMM_SMEM (2 * STAGE_B)

__device__ __forceinline__ void gload_stage(
    uint32_t sb, const __half* Ahi, const __half* Alo, int lda,
    const __half* Bh, int bm, int bn, int k0, int K, int N, int tid)
{
    #pragma unroll
    for (int idx = tid; idx < 512; idx += 256) {
        const int r = idx >> 2, c = idx & 3;
        const uint32_t so = (uint32_t)(r * LDP * 2 + c * 16);
        const size_t ga = (size_t)(bm + r) * lda + k0 + c * 8;
        cp16(sb + 0 * TILE_B + so, Ahi + ga);
        cp16(sb + 1 * TILE_B + so, Alo + ga);
        const bool v = (bn + r) < N;
        const size_t gb = v ? ((size_t)(bn + r) * K + k0 + c * 8) : 0;
        cp16_pred(sb + 2 * TILE_B + so, Bh + gb, v);
    }
}

template <bool QROPE>
__device__ __forceinline__ void gemm_body(
    uint32_t sbase,
    const __half* __restrict__ Ahi, const __half* __restrict__ Alo, int lda,
    const __half* __restrict__ Bh,
    float* __restrict__ C, __half* __restrict__ Chi, __half* __restrict__ Clo,
    const float2* __restrict__ rope,
    int N, int K, int ldc, int bm, int bn, int c0)
{
    const int tid  = threadIdx.x;
    const int wid  = tid >> 5;
    const int lane = tid & 31;
    const int warp_m = (wid >> 2) * 64;
    const int warp_n = (wid & 3) * 32;
    const int nk = K / 32;

    float acc[4][4][4];
    #pragma unroll
    for (int i = 0; i < 4; ++i)
        #pragma unroll
        for (int j = 0; j < 4; ++j)
            #pragma unroll
            for (int q = 0; q < 4; ++q) acc[i][j][q] = 0.f;

    gload_stage(sbase, Ahi, Alo, lda, Bh, bm, bn, 0, K, N, tid);
    cp_commit();

    const int a_row = lane & 15;
    const int a_coff = (lane >> 4) << 3;
    const int b_row = lane & 7;
    const int b_coff = ((lane >> 3) & 1) << 3;

    for (int i = 0; i < nk; ++i) {
        if (i + 1 < nk) {
            gload_stage(sbase + ((i + 1) & 1) * STAGE_B, Ahi, Alo, lda, Bh,
                        bm, bn, (i + 1) * 32, K, N, tid);
            cp_commit();
            asm volatile("cp.async.wait_group 1;" ::: "memory");
        } else {
            asm volatile("cp.async.wait_group 0;" ::: "memory");
        }
        __syncthreads();

        const uint32_t sb = sbase + (i & 1) * STAGE_B;
        #pragma unroll
        for (int kc = 0; kc < 2; ++kc) {
            const int kel = kc * 16;
            uint32_t ah[4][4], al[4][4];
            #pragma unroll
            for (int mi = 0; mi < 4; ++mi) {
                const uint32_t ao = (uint32_t)((warp_m + mi * 16 + a_row) * LDP
                                               + kel + a_coff) * 2;
                ldm_x4(ah[mi], sb + ao);
                ldm_x4(al[mi], sb + TILE_B + ao);
            }
            #pragma unroll
            for (int ni = 0; ni < 4; ++ni) {
                const uint32_t bo = (uint32_t)((warp_n + ni * 8 + b_row) * LDP
                                               + kel + b_coff) * 2;
                uint32_t bh[2];
                ldm_x2(bh[0], bh[1], sb + 2 * TILE_B + bo);
                #pragma unroll
                for (int mi = 0; mi < 4; ++mi) {
                    mma_f16(acc[mi][ni], ah[mi], bh);
                    mma_f16(acc[mi][ni], al[mi], bh);
                }
            }
        }
        __syncthreads();
    }

    const int er = lane >> 2;
    const int ec = (lane & 3) * 2;
    #pragma unroll
    for (int mi = 0; mi < 4; ++mi) {
        #pragma unroll
        for (int ni = 0; ni < 4; ++ni) {
            const int col = bn + warp_n + ni * 8 + ec;
            if (col < N) {
                const int r0 = bm + warp_m + mi * 16 + er;
                const float a0 = acc[mi][ni][0], a1 = acc[mi][ni][1];
                const float a2 = acc[mi][ni][2], a3 = acc[mi][ni][3];
                if (QROPE) {
                    const int d = col & 127;
                    #pragma unroll
                    for (int rr = 0; rr < 2; ++rr) {
                        const int r = r0 + rr * 8;
                        float u0 = rr ? a2 : a0;
                        float u1 = rr ? a3 : a1;
                        if (d >= 64) {
                            const int t = (d - 64) >> 1;
                            const float2 cs = rope[(r & 2047) * 32 + t];
                            const float w0 = u0 * cs.x - u1 * cs.y;
                            const float w1 = u1 * cs.x + u0 * cs.y;
                            u0 = w0; u1 = w1;
                        }
                        *(uint32_t*)(Chi + (size_t)r * ldc + col) = pack_h2(u0, u1);
                        *(uint32_t*)(Clo + (size_t)r * ldc + col) =
                            pack_h2(h_res(u0), h_res(u1));
                    }
                } else {
                    if (C && col >= c0) {
                        *(float2*)(C + (size_t)r0 * ldc + col) = make_float2(a0, a1);
                        *(float2*)(C + (size_t)(r0 + 8) * ldc + col) =
                            make_float2(a2, a3);
                    }
                    if (Chi) {
                        *(uint32_t*)(Chi + (size_t)r0 * ldc + col) = pack_h2(a0, a1);
                        *(uint32_t*)(Chi + (size_t)(r0 + 8) * ldc + col) =
                            pack_h2(a2, a3);
                        if (Clo) {
                            *(uint32_t*)(Clo + (size_t)r0 * ldc + col) =
                                pack_h2(h_res(a0), h_res(a1));
                            *(uint32_t*)(Clo + (size_t)(r0 + 8) * ldc + col) =
                                pack_h2(h_res(a2), h_res(a3));
                        }
                    }
                }
            }
        }
    }
}

__global__ __launch_bounds__(256, 2)
void gemm_one(const __half* __restrict__ Ahi, const __half* __restrict__ Alo,
              int lda, const __half* __restrict__ Bh,
              float* __restrict__ C, __half* __restrict__ Chi,
              __half* __restrict__ Clo, int N, int K, int ldc, int c0)
{
    extern __shared__ char smraw[];
    gemm_body<false>(cvta_s(smraw), Ahi, Alo, lda, Bh, C, Chi, Clo, nullptr,
                     N, K, ldc, blockIdx.y * 128, blockIdx.x * 128, c0);
}

// grouped: Q-GEMM (rope epilogue -> Qb hi/lo) + KVB-GEMM (fp16 hi-only)
__global__ __launch_bounds__(256, 2)
void gemm_two(const __half* A1h, const __half* A1l, int lda1, const __half* B1,
              __half* Q_hi, __half* Q_lo, const float2* rope,
              int N1, int K1, int ldc1,
              const __half* A2h, const __half* A2l, int lda2, const __half* B2,
              __half* C2h, int N2, int K2, int ldc2, int bx_split)
{
    extern __shared__ char smraw[];
    const uint32_t sb = cvta_s(smraw);
    if ((int)blockIdx.x < bx_split)
        gemm_body<true>(sb, A1h, A1l, lda1, B1, nullptr, Q_hi, Q_lo, rope,
                        N1, K1, ldc1, blockIdx.y * 128, blockIdx.x * 128, 0);
    else
        gemm_body<false>(sb, A2h, A2l, lda2, B2, nullptr, C2h, nullptr, nullptr,
                         N2, K2, ldc2, blockIdx.y * 128,
                         (blockIdx.x - bx_split) * 128, 0);
}

// ---------------------------------------------------------------------------
// Grouped fp32 -> fp16 conversion + rope table — identical to R13
// ---------------------------------------------------------------------------
union HV4 { __half h[4]; ushort4 u; };

#define NV4_X   (MROWS * EMB / 4)
#define NV4_QA  (QRANK * EMB / 4)
#define NV4_KVA (576 * EMB / 4)
#define NV4_QB  ((NHEAD * QK_D) * QRANK / 4)
#define NV4_KVB (3072 * KVRANK / 4)
#define NV4_OW  (EMB * (NHEAD * V_D) / 4)
#define C1_ (NV4_X)
#define C2_ (C1_ + NV4_QA)
#define C3_ (C2_ + NV4_KVA)
#define C4_ (C3_ + NV4_QB)
#define C5_ (C4_ + NV4_KVB)
#define C6_ (C5_ + NV4_OW)
#define C7_ (C6_ + SLEN * 32)
#define SPLIT_BLOCKS ((C7_ + 255) / 256)

__global__ void split_all(const float* __restrict__ x,  const float* __restrict__ qa,
                          const float* __restrict__ kva, const float* __restrict__ qb,
                          const float* __restrict__ kvb, const float* __restrict__ ow,
                          __half* __restrict__ xh,  __half* __restrict__ xl,
                          __half* __restrict__ qkh, __half* __restrict__ qbh,
                          __half* __restrict__ kvbh, __half* __restrict__ owh,
                          float2* __restrict__ rope)
{
    const int i = blockIdx.x * blockDim.x + threadIdx.x;
    if (i >= C7_) return;

    if (i >= C6_) {
        const int e = i - C6_;
        const int s = e >> 5, t = e & 31;
        const float theta = powf(10000.f, -((float)(2 * t)) / 64.f);
        float sn, cs;
        sincosf((float)s * theta, &sn, &cs);
        rope[e] = make_float2(cs, sn);
        return;
    }

    const float* src; __half* hi; int o; bool do_lo = false;
    if (i < C1_)      { src = x;   hi = xh;   o = i;       do_lo = true; }
    else if (i < C2_) { src = qa;  hi = qkh;  o = i - C1_; }
    else if (i < C3_) { src = kva; hi = qkh + (size_t)QRANK * EMB; o = i - C2_; }
    else if (i < C4_) { src = qb;  hi = qbh;  o = i - C3_; }
    else if (i < C5_) { src = kvb; hi = kvbh; o = i - C4_; }
    else              { src = ow;  hi = owh;  o = i - C5_; }

    const float4 v = ((const float4*)src)[o];
    const float vv[4] = { v.x, v.y, v.z, v.w };
    HV4 H;
    #pragma unroll
    for (int j = 0; j < 4; ++j) H.h[j] = __float2half_rn(vv[j]);
    ((ushort4*)hi)[o] = H.u;
    if (do_lo) {
        HV4 L;
        #pragma unroll
        for (int j = 0; j < 4; ++j)
            L.h[j] = __float2half_rn(vv[j] - __half2float(H.h[j]));
        ((ushort4*)xl)[o] = L.u;
    }
}

// ---------------------------------------------------------------------------
// Fused repack: K (fp16 copy + rope from XC) + V transpose. Q path removed.
// Blocks 0..MROWS-1 = K; MROWS..MROWS+1023 = V transpose.
// ---------------------------------------------------------------------------
__global__ __launch_bounds__(1024)
void repack_all(const __half* __restrict__ KVBh, const float* __restrict__ XC,
                const float2* __restrict__ rope,
                __half* __restrict__ Kh, __half* __restrict__ Vh)
{
    __shared__ __half tile[64][136];
    const int bb = blockIdx.x;
    const int tid = threadIdx.x;

    if (bb < MROWS) {
        const int bs = bb;
        const int b  = bs >> 11;
        const int s  = bs & 2047;
        const int h  = tid >> 6;          // 0..15
        const int t  = tid & 63;          // pair index
        const size_t dst = ((size_t)(b * NHEAD + h) * SLEN + s) * QK_D + 2 * t;

        if (t < 32) {
            *(uint32_t*)(Kh + dst) =
                *(const uint32_t*)(KVBh + (size_t)bs * 3072 + h * 192 + 2 * t);
        } else {
            const int tr = t - 32;
            const float2 cs = rope[s * 32 + tr];
            const float* kr = XC + (size_t)bs * NXC + 2048;
            const float2 p = *(const float2*)(kr + 2 * tr);
            const float v0 = p.x * cs.x - p.y * cs.y;
            const float v1 = p.y * cs.x + p.x * cs.y;
            *(uint32_t*)(Kh + dst) = pack_h2(v0, v1);
        }
    } else {
        const int idx = bb - MROWS;
        const int bh  = idx >> 5;
        const int s0  = (idx & 31) * 64;
        const int b   = bh >> 4;
        const int h   = bh & 15;

        {
            const int r = tid >> 4;
            const int c = (tid & 15) * 8;
            const uint4 v = *(const uint4*)(KVBh + (size_t)(b * SLEN + s0 + r) * 3072
                                            + h * 192 + 64 + c);
            *(uint4*)&tile[r][c] = v;
        }
        __syncthreads();

        const int d = tid >> 3;
        const int chunk = tid & 7;
        const size_t obase = ((size_t)bh * 128 + d) * SLEN + s0 + chunk * 8;
        #pragma unroll
        for (int j = 0; j < 8; j += 2) {
            const uint32_t w = (uint32_t)__half_as_ushort(tile[chunk * 8 + j][d])
                             | ((uint32_t)__half_as_ushort(tile[chunk * 8 + j + 1][d]) << 16);
            *(uint32_t*)(Vh + obase + j) = w;
        }
    }
}

// ---------------------------------------------------------------------------
// Flash attention — R13 config; Q read from [bs][h*128+d] layout (stride 2048)
// ---------------------------------------------------------------------------
#define QLDE 136
#define VLDE 72
#define OFF_QH 0
#define OFF_QL 17408
#define OFF_STG 34816
#define STG_SZ 35840
#define SOFF_KH 0
#define SOFF_VH 17408
#define FLASH_SMEM (OFF_STG + 2 * STG_SZ)   // 106496

__device__ __forceinline__ void fa_load_kv(
    uint32_t base, const __half* Kh, const __half* Vh, int bh, int kt, int tid)
{
    const size_t gk = ((size_t)bh * SLEN + kt * 64) * QK_D;
    #pragma unroll
    for (int i = tid; i < 1024; i += 128) {
        const int r = i >> 4, c = (i & 15) * 8;
        cp16(base + SOFF_KH + (uint32_t)(r * QLDE + c) * 2,
             Kh + gk + (size_t)r * QK_D + c);
    }
    const size_t gv = (size_t)bh * V_D * SLEN + kt * 64;
    #pragma unroll
    for (int i = tid; i < 1024; i += 128) {
        const int r = i >> 3, c = (i & 7) * 8;
        cp16(base + SOFF_VH + (uint32_t)(r * VLDE + c) * 2,
             Vh + gv + (size_t)r * SLEN + c);
    }
}

__global__ __launch_bounds__(128, 2)
void flash_mma(const __half* __restrict__ Qh, const __half* __restrict__ Ql,
               const __half* __restrict__ Kh, const __half* __restrict__ Vh,
               __half* __restrict__ Ohi, __half* __restrict__ Olo)
{
    extern __shared__ char smraw[];
    const uint32_t sb0 = cvta_s(smraw);

    const int tid  = threadIdx.x;
    const int wid  = tid >> 5;
    const int lane = tid & 31;
    const int bh = blockIdx.y;
    const int b  = bh >> 4;
    const int h  = bh & 15;
    const int q0 = blockIdx.x * 64;
    const int r_base = wid * 16;

    // Q tile from [bs][h*128+d] layout: base (b*SLEN+q0)*2048 + h*128, stride 2048
    const size_t gq = ((size_t)(b * SLEN + q0)) * (NHEAD * QK_D) + h * QK_D;
    #pragma unroll
    for (int i = tid; i < 1024; i += 128) {
        const int r = i >> 4, c = (i & 15) * 8;
        const uint32_t so = (uint32_t)(r * QLDE + c) * 2;
        cp16(sb0 + OFF_QH + so, Qh + gq + (size_t)r * (NHEAD * QK_D) + c);
        cp16(sb0 + OFF_QL + so, Ql + gq + (size_t)r * (NHEAD * QK_D) + c);
    }
    fa_load_kv(sb0 + OFF_STG, Kh, Vh, bh, 0, tid);
    cp_commit();
    asm volatile("cp.async.wait_group 0;" ::: "memory");
    __syncthreads();

    uint32_t qfh[8][4], qfl[8][4];
    {
        const int ar = lane & 15;
        const int ac = ((lane >> 4) & 1) * 8;
        #pragma unroll
        for (int kf = 0; kf < 8; ++kf) {
            const uint32_t off = (uint32_t)((r_base + ar) * QLDE + kf * 16 + ac) * 2;
            ldm_x4(qfh[kf], sb0 + OFF_QH + off);
            ldm_x4(qfl[kf], sb0 + OFF_QL + off);
        }
    }

    float Oa[16][4];
    #pragma unroll
    for (int i = 0; i < 16; ++i)
        #pragma unroll
        for (int j = 0; j < 4; ++j) Oa[i][j] = 0.f;
    float m0 = -INFINITY, m1 = -INFINITY, l0 = 0.f, l1 = 0.f;

    const int krow = lane & 7;
    const int kcol = ((lane >> 3) & 3) * 8;

    for (int kt = 0; kt < SLEN / 64; ++kt) {
        if (kt + 1 < SLEN / 64) {
            fa_load_kv(sb0 + OFF_STG + ((kt + 1) & 1) * STG_SZ, Kh, Vh, bh, kt + 1, tid);
            cp_commit();
            asm volatile("cp.async.wait_group 1;" ::: "memory");
        } else {
            asm volatile("cp.async.wait_group 0;" ::: "memory");
        }
        __syncthreads();

        const uint32_t sk = sb0 + OFF_STG + (kt & 1) * STG_SZ;

        float S[8][4];
        #pragma unroll
        for (int i = 0; i < 8; ++i)
            #pragma unroll
            for (int j = 0; j < 4; ++j) S[i][j] = 0.f;

        #pragma unroll
        for (int nb = 0; nb < 8; ++nb) {
            #pragma unroll
            for (int kfp = 0; kfp < 4; ++kfp) {
                const uint32_t ko = (uint32_t)((nb * 8 + krow) * QLDE
                                               + kfp * 32 + kcol) * 2;
                uint32_t kfh[4];
                ldm_x4(kfh, sk + SOFF_KH + ko);
                mma_f16(S[nb], qfh[2 * kfp],     kfh);
                mma_f16(S[nb], qfh[2 * kfp + 1], kfh + 2);
                mma_f16(S[nb], qfl[2 * kfp],     kfh);
                mma_f16(S[nb], qfl[2 * kfp + 1], kfh + 2);
            }
        }

        float mx0 = -INFINITY, mx1 = -INFINITY;
        #pragma unroll
        for (int nb = 0; nb < 8; ++nb) {
            mx0 = fmaxf(mx0, fmaxf(S[nb][0], S[nb][1]));
            mx1 = fmaxf(mx1, fmaxf(S[nb][2], S[nb][3]));
        }
        mx0 = fmaxf(mx0, __shfl_xor_sync(0xffffffffu, mx0, 1));
        mx0 = fmaxf(mx0, __shfl_xor_sync(0xffffffffu, mx0, 2));
        mx1 = fmaxf(mx1, __shfl_xor_sync(0xffffffffu, mx1, 1));
        mx1 = fmaxf(mx1, __shfl_xor_sync(0xffffffffu, mx1, 2));

        const float mn0 = fmaxf(m0, mx0);
        const float mn1 = fmaxf(m1, mx1);
        const float f0 = __expf(m0 - mn0);
        const float f1 = __expf(m1 - mn1);
        m0 = mn0; m1 = mn1;

        float rs0 = 0.f, rs1 = 0.f;
        #pragma unroll
        for (int nb = 0; nb < 8; ++nb) {
            S[nb][0] = __expf(S[nb][0] - mn0);
            S[nb][1] = __expf(S[nb][1] - mn0);
            S[nb][2] = __expf(S[nb][2] - mn1);
            S[nb][3] = __expf(S[nb][3] - mn1);
            rs0 += S[nb][0] + S[nb][1];
            rs1 += S[nb][2] + S[nb][3];
        }
        rs0 += __shfl_xor_sync(0xffffffffu, rs0, 1);
        rs0 += __shfl_xor_sync(0xffffffffu, rs0, 2);
        rs1 += __shfl_xor_sync(0xffffffffu, rs1, 1);
        rs1 += __shfl_xor_sync(0xffffffffu, rs1, 2);
        l0 = l0 * f0 + rs0;
        l1 = l1 * f1 + rs1;

        #pragma unroll
        for (int i = 0; i < 16; ++i) {
            Oa[i][0] *= f0; Oa[i][1] *= f0;
            Oa[i][2] *= f1; Oa[i][3] *= f1;
        }

        uint32_t ph[4][4], pl[4][4];
        #pragma unroll
        for (int kf2 = 0; kf2 < 4; ++kf2) {
            const float* s0p = S[2 * kf2];
            const float* s1p = S[2 * kf2 + 1];
            ph[kf2][0] = pack_h2(s0p[0], s0p[1]);
            ph[kf2][1] = pack_h2(s0p[2], s0p[3]);
            ph[kf2][2] = pack_h2(s1p[0], s1p[1]);
            ph[kf2][3] = pack_h2(s1p[2], s1p[3]);
            pl[kf2][0] = pack_h2(h_res(s0p[0]), h_res(s0p[1]));
            pl[kf2][1] = pack_h2(h_res(s0p[2]), h_res(s0p[3]));
            pl[kf2][2] = pack_h2(h_res(s1p[0]), h_res(s1p[1]));
            pl[kf2][3] = pack_h2(h_res(s1p[2]), h_res(s1p[3]));
        }

        #pragma unroll
        for (int nb2 = 0; nb2 < 16; ++nb2) {
            #pragma unroll
            for (int kfp2 = 0; kfp2 < 2; ++kfp2) {
                const uint32_t vo = (uint32_t)((nb2 * 8 + krow) * VLDE
                                               + kfp2 * 32 + kcol) * 2;
                uint32_t vfh[4];
                ldm_x4(vfh, sk + SOFF_VH + vo);
                mma_f16(Oa[nb2], ph[2 * kfp2],     vfh);
                mma_f16(Oa[nb2], ph[2 * kfp2 + 1], vfh + 2);
                mma_f16(Oa[nb2], pl[2 * kfp2],     vfh);
                mma_f16(Oa[nb2], pl[2 * kfp2 + 1], vfh + 2);
            }
        }
        __syncthreads();
    }

    const float inv0 = 1.f / l0;
    const float inv1 = 1.f / l1;
    const int er = lane >> 2;
    const int ec = (lane & 3) * 2;
    const size_t row0 = (size_t)(b * SLEN + q0 + r_base + er) * (NHEAD * V_D) + h * V_D;
    const size_t row1 = row0 + (size_t)8 * (NHEAD * V_D);
    #pragma unroll
    for (int nb2 = 0; nb2 < 16; ++nb2) {
        const int col = nb2 * 8 + ec;
        const float a0 = Oa[nb2][0] * inv0, a1 = Oa[nb2][1] * inv0;
        const float a2 = Oa[nb2][2] * inv1, a3 = Oa[nb2][3] * inv1;
        *(uint32_t*)(Ohi + row0 + col) = pack_h2(a0, a1);
        *(uint32_t*)(Olo + row0 + col) = pack_h2(h_res(a0), h_res(a1));
        *(uint32_t*)(Ohi + row1 + col) = pack_h2(a2, a3);
        *(uint32_t*)(Olo + row1 + col) = pack_h2(h_res(a2), h_res(a3));
    }
}

// ---------------------------------------------------------------------------
extern "C" void kernel_launch(void* const* d_in, const int* in_sizes, int n_in,
                              void* d_out, int out_size)
{
    const float* x    = (const float*)d_in[0];
    const float* q_a  = (const float*)d_in[1];
    const float* q_b  = (const float*)d_in[2];
    const float* kv_a = (const float*)d_in[3];
    const float* kv_b = (const float*)d_in[4];
    const float* o_w  = (const float*)d_in[5];
    float* out = (float*)d_out;

    float *XC;
    float2* rope;
    cudaGetSymbolAddress((void**)&XC,   g_XC);
    cudaGetSymbolAddress((void**)&rope, g_rope);

    __half *x_hi, *x_lo, *qk_h, *qb_h, *kvb_h, *ow_h, *XC_hi, *XC_lo, *KVBh;
    __half *Qb_hi, *Qb_lo, *Kb_h, *Vt_h, *O_hi, *O_lo;
    cudaGetSymbolAddress((void**)&x_hi,  g_x_hi);
    cudaGetSymbolAddress((void**)&x_lo,  g_x_lo);
    cudaGetSymbolAddress((void**)&qk_h,  g_qakva_h);
    cudaGetSymbolAddress((void**)&qb_h,  g_qb_h);
    cudaGetSymbolAddress((void**)&kvb_h, g_kvb_h);
    cudaGetSymbolAddress((void**)&ow_h,  g_ow_h);
    cudaGetSymbolAddress((void**)&XC_hi, g_XC_hi);
    cudaGetSymbolAddress((void**)&XC_lo, g_XC_lo);
    cudaGetSymbolAddress((void**)&KVBh,  g_KVBh);
    cudaGetSymbolAddress((void**)&Qb_hi, g_Qb_hi);
    cudaGetSymbolAddress((void**)&Qb_lo, g_Qb_lo);
    cudaGetSymbolAddress((void**)&Kb_h,  g_Kb_h);
    cudaGetSymbolAddress((void**)&Vt_h,  g_Vt_h);
    cudaGetSymbolAddress((void**)&O_hi,  g_O_hi);
    cudaGetSymbolAddress((void**)&O_lo,  g_O_lo);

    cudaFuncSetAttribute(gemm_one, cudaFuncAttributeMaxDynamicSharedMemorySize,
                         GEMM_SMEM);
    cudaFuncSetAttribute(gemm_two, cudaFuncAttributeMaxDynamicSharedMemorySize,
                         GEMM_SMEM);
    cudaFuncSetAttribute(flash_mma, cudaFuncAttributeMaxDynamicSharedMemorySize,
                         FLASH_SMEM);

    // 1) conversions + rope table (single launch)
    split_all<<<SPLIT_BLOCKS, 256>>>(x, q_a, kv_a, q_b, kv_b, o_w,
                                     x_hi, x_lo, qk_h, qb_h, kvb_h, ow_h, rope);

    // 2) merged x-GEMM: XC = x @ [q_a; kv_a]^T (fp32 only for k_rot cols >=2048)
    gemm_one<<<dim3(17, 32), 256, GEMM_SMEM>>>(x_hi, x_lo, EMB, qk_h,
                                               XC, XC_hi, XC_lo, NXC, EMB, NXC, 2048);

    // 3) grouped: Q-GEMM (rope epilogue -> Qb hi/lo)  +  KVB-GEMM (fp16)
    gemm_two<<<dim3(16 + 24, 32), 256, GEMM_SMEM>>>(
        XC_hi, XC_lo, NXC, qb_h, Qb_hi, Qb_lo, rope, 2048, QRANK, 2048,
        XC_hi + QRANK, XC_lo + QRANK, NXC, kvb_h, KVBh, 3072, KVRANK, 3072,
        16);

    // 4) fused repack (K + V transpose only)
    repack_all<<<MROWS + 1024, 1024>>>(KVBh, XC, rope, Kb_h, Vt_h);

    // 5) attention (Q read with stride 2048)
    flash_mma<<<dim3(SLEN / 64, BHN), 128, FLASH_SMEM>>>(
        Qb_hi, Qb_lo, Kb_h, Vt_h, O_hi, O_lo);

    // 6) out = O @ o_w^T
    gemm_one<<<dim3(16, 32), 256, GEMM_SMEM>>>(O_hi, O_lo, EMB, ow_h,
                                               out, nullptr, nullptr,
                                               EMB, NHEAD * V_D, EMB, 0);
}

// round 15
// speedup vs baseline: 1.1299x; 1.0184x over previous
#include <cuda_runtime.h>
#include <cuda_fp16.h>
#include <math.h>
#include <stdint.h>

// ---------------------------------------------------------------------------
// Problem constants
// ---------------------------------------------------------------------------
#define BATCH   2
#define SLEN    2048
#define EMB     2048
#define NHEAD   16
#define QRANK   1536
#define KVRANK  512
#define QK_D    128
#define V_D     128
#define MROWS   (BATCH * SLEN)        // 4096
#define BHN     (BATCH * NHEAD)       // 32
#define NXC     (QRANK + 576)         // 2112

// ------------------------- fp32 scratch -----------------------------------
__device__ float  g_XC [(size_t)MROWS * NXC];           // only cols >=2048 written/read
__device__ float2 g_rope[SLEN * 32];                    // (cos, sin)

// ------------------------- fp16 buffers -----------------------------------
__device__ __half g_x_hi   [(size_t)MROWS * EMB];
__device__ __half g_x_lo   [(size_t)MROWS * EMB];
__device__ __half g_qakva_h[(size_t)NXC * EMB];
__device__ __half g_qb_h   [(size_t)(NHEAD * QK_D) * QRANK];
__device__ __half g_kvb_h  [(size_t)3072 * KVRANK];
__device__ __half g_ow_h   [(size_t)EMB * (NHEAD * V_D)];
__device__ __half g_XC_hi  [(size_t)MROWS * NXC];
__device__ __half g_XC_lo  [(size_t)MROWS * NXC];
__device__ __half g_KVBh   [(size_t)MROWS * 3072];
__device__ __half g_Qb_hi  [(size_t)MROWS * (NHEAD * QK_D)];
__device__ __half g_Qb_lo  [(size_t)MROWS * (NHEAD * QK_D)];
__device__ __half g_Kb_h   [(size_t)BHN * SLEN * QK_D];
__device__ __half g_Vt_h   [(size_t)BHN * V_D * SLEN];
__device__ __half g_O_hi   [(size_t)MROWS * (NHEAD * V_D)];
__device__ __half g_O_lo   [(size_t)MROWS * (NHEAD * V_D)];

// ---------------------------------------------------------------------------
// PTX helpers
// ---------------------------------------------------------------------------
__device__ __forceinline__ uint32_t cvta_s(const void* p) {
    return (uint32_t)__cvta_generic_to_shared(p);
}
__device__ __forceinline__ void cp16(uint32_t dst, const void* src) {
    asm volatile("cp.async.cg.shared.global [%0], [%1], 16;"
                 :: "r"(dst), "l"(src) : "memory");
}
__device__ __forceinline__ void cp16_pred(uint32_t dst, const void* src, bool valid) {
    const int sz = valid ? 16 : 0;
    asm volatile("cp.async.cg.shared.global [%0], [%1], 16, %2;"
                 :: "r"(dst), "l"(src), "r"(sz) : "memory");
}
__device__ __forceinline__ void cp_commit() {
    asm volatile("cp.async.commit_group;" ::: "memory");
}
__device__ __forceinline__ void ldm_x4(uint32_t* r, uint32_t addr) {
    asm volatile("ldmatrix.sync.aligned.m8n8.x4.shared.b16 {%0,%1,%2,%3}, [%4];"
                 : "=r"(r[0]), "=r"(r[1]), "=r"(r[2]), "=r"(r[3]) : "r"(addr));
}
__device__ __forceinline__ void ldm_x2(uint32_t& r0, uint32_t& r1, uint32_t addr) {
    asm volatile("ldmatrix.sync.aligned.m8n8.x2.shared.b16 {%0,%1}, [%2];"
                 : "=r"(r0), "=r"(r1) : "r"(addr));
}
__device__ __forceinline__ void mma_f16(float* c, const uint32_t* a,
                                        const uint32_t* b) {
    asm volatile(
        "mma.sync.aligned.m16n8k16.row.col.f32.f16.f16.f32 "
        "{%0,%1,%2,%3}, {%4,%5,%6,%7}, {%8,%9}, {%0,%1,%2,%3};"
        : "+f"(c[0]), "+f"(c[1]), "+f"(c[2]), "+f"(c[3])
        : "r"(a[0]), "r"(a[1]), "r"(a[2]), "r"(a[3]), "r"(b[0]), "r"(b[1]));
}
__device__ __forceinline__ uint32_t pack_h2(float lo, float hi) {
    uint32_t r;
    asm("cvt.rn.f16x2.f32 %0, %1, %2;" : "=r"(r) : "f"(hi), "f"(lo));
    return r;
}
__device__ __forceinline__ float h_res(float v) {
    return v - __half2float(__float2half_rn(v));
}

// ---------------------------------------------------------------------------
// HMMA 2-term fp16 GEMM (NT). Warp tile 32x64 (4m x 2n layout):
// per kc: A = 4 ldm_x4 (2 mi x hi/lo), B = 8 ldm_x2 -> 4KB frag traffic (-20%).
// Epilogue modes as R14.
// ---------------------------------------------------------------------------
#define LDP 40
#define TILE_B (128 * LDP * 2)
#define STAGE_B (3 * TILE_B)
#define GEMM_SMEM (2 * STAGE_B)

__device__ __forceinline__ void gload_stage(
    uint32_t sb, const __half* Ahi, const __half* Alo, int lda,
    const __half* Bh, int bm, int bn, int k0, int K, int N, int tid)
{
    #pragma unroll
    for (int idx = tid; idx < 512; idx += 256) {
        const int r = idx >> 2, c = idx & 3;
        const uint32_t so = (uint32_t)(r * LDP * 2 + c * 16);
        const size_t ga = (size_t)(bm + r) * lda + k0 + c * 8;
        cp16(sb + 0 * TILE_B + so, Ahi + ga);
        cp16(sb + 1 * TILE_B + so, Alo + ga);
        const bool v = (bn + r) < N;
        const size_t gb = v ? ((size_t)(bn + r) * K + k0 + c * 8) : 0;
        cp16_pred(sb + 2 * TILE_B + so, Bh + gb, v);
    }
}

template <bool QROPE>
__device__ __forceinline__ void gemm_body(
    uint32_t sbase,
    const __half* __restrict__ Ahi, const __half* __restrict__ Alo, int lda,
    const __half* __restrict__ Bh,
    float* __restrict__ C, __half* __restrict__ Chi, __half* __restrict__ Clo,
    const float2* __restrict__ rope,
    int N, int K, int ldc, int bm, int bn, int c0)
{
    const int tid  = threadIdx.x;
    const int wid  = tid >> 5;
    const int lane = tid & 31;
    const int warp_m = (wid >> 1) * 32;     // 0,32,64,96
    const int warp_n = (wid & 1) * 64;      // 0,64
    const int nk = K / 32;

    float acc[2][8][4];
    #pragma unroll
    for (int i = 0; i < 2; ++i)
        #pragma unroll
        for (int j = 0; j < 8; ++j)
            #pragma unroll
            for (int q = 0; q < 4; ++q) acc[i][j][q] = 0.f;

    gload_stage(sbase, Ahi, Alo, lda, Bh, bm, bn, 0, K, N, tid);
    cp_commit();

    const int a_row = lane & 15;
    const int a_coff = (lane >> 4) << 3;
    const int b_row = lane & 7;
    const int b_coff = ((lane >> 3) & 1) << 3;

    for (int i = 0; i < nk; ++i) {
        if (i + 1 < nk) {
            gload_stage(sbase + ((i + 1) & 1) * STAGE_B, Ahi, Alo, lda, Bh,
                        bm, bn, (i + 1) * 32, K, N, tid);
            cp_commit();
            asm volatile("cp.async.wait_group 1;" ::: "memory");
        } else {
            asm volatile("cp.async.wait_group 0;" ::: "memory");
        }
        __syncthreads();

        const uint32_t sb = sbase + (i & 1) * STAGE_B;
        #pragma unroll
        for (int kc = 0; kc < 2; ++kc) {
            const int kel = kc * 16;
            uint32_t ah[2][4], al[2][4];
            #pragma unroll
            for (int mi = 0; mi < 2; ++mi) {
                const uint32_t ao = (uint32_t)((warp_m + mi * 16 + a_row) * LDP
                                               + kel + a_coff) * 2;
                ldm_x4(ah[mi], sb + ao);
                ldm_x4(al[mi], sb + TILE_B + ao);
            }
            #pragma unroll
            for (int ni = 0; ni < 8; ++ni) {
                const uint32_t bo = (uint32_t)((warp_n + ni * 8 + b_row) * LDP
                                               + kel + b_coff) * 2;
                uint32_t bh[2];
                ldm_x2(bh[0], bh[1], sb + 2 * TILE_B + bo);
                #pragma unroll
                for (int mi = 0; mi < 2; ++mi) {
                    mma_f16(acc[mi][ni], ah[mi], bh);
                    mma_f16(acc[mi][ni], al[mi], bh);
                }
            }
        }
        __syncthreads();
    }

    const int er = lane >> 2;
    const int ec = (lane & 3) * 2;
    #pragma unroll
    for (int mi = 0; mi < 2; ++mi) {
        #pragma unroll
        for (int ni = 0; ni < 8; ++ni) {
            const int col = bn + warp_n + ni * 8 + ec;
            if (col < N) {
                const int r0 = bm + warp_m + mi * 16 + er;
                const float a0 = acc[mi][ni][0], a1 = acc[mi][ni][1];
                const float a2 = acc[mi][ni][2], a3 = acc[mi][ni][3];
                if (QROPE) {
                    const int d = col & 127;
                    #pragma unroll
                    for (int rr = 0; rr < 2; ++rr) {
                        const int r = r0 + rr * 8;
                        float u0 = rr ? a2 : a0;
                        float u1 = rr ? a3 : a1;
                        if (d >= 64) {
                            const int t = (d - 64) >> 1;
                            const float2 cs = rope[(r & 2047) * 32 + t];
                            const float w0 = u0 * cs.x - u1 * cs.y;
                            const float w1 = u1 * cs.x + u0 * cs.y;
                            u0 = w0; u1 = w1;
                        }
                        *(uint32_t*)(Chi + (size_t)r * ldc + col) = pack_h2(u0, u1);
                        *(uint32_t*)(Clo + (size_t)r * ldc + col) =
                            pack_h2(h_res(u0), h_res(u1));
                    }
                } else {
                    if (C && col >= c0) {
                        *(float2*)(C + (size_t)r0 * ldc + col) = make_float2(a0, a1);
                        *(float2*)(C + (size_t)(r0 + 8) * ldc + col) =
                            make_float2(a2, a3);
                    }
                    if (Chi) {
                        *(uint32_t*)(Chi + (size_t)r0 * ldc + col) = pack_h2(a0, a1);
                        *(uint32_t*)(Chi + (size_t)(r0 + 8) * ldc + col) =
                            pack_h2(a2, a3);
                        if (Clo) {
                            *(uint32_t*)(Clo + (size_t)r0 * ldc + col) =
                                pack_h2(h_res(a0), h_res(a1));
                            *(uint32_t*)(Clo + (size_t)(r0 + 8) * ldc + col) =
                                pack_h2(h_res(a2), h_res(a3));
                        }
                    }
                }
            }
        }
    }
}

__global__ __launch_bounds__(256, 2)
void gemm_one(const __half* __restrict__ Ahi, const __half* __restrict__ Alo,
              int lda, const __half* __restrict__ Bh,
              float* __restrict__ C, __half* __restrict__ Chi,
              __half* __restrict__ Clo, int N, int K, int ldc, int c0)
{
    extern __shared__ char smraw[];
    gemm_body<false>(cvta_s(smraw), Ahi, Alo, lda, Bh, C, Chi, Clo, nullptr,
                     N, K, ldc, blockIdx.y * 128, blockIdx.x * 128, c0);
}

__global__ __launch_bounds__(256, 2)
void gemm_two(const __half* A1h, const __half* A1l, int lda1, const __half* B1,
              __half* Q_hi, __half* Q_lo, const float2* rope,
              int N1, int K1, int ldc1,
              const __half* A2h, const __half* A2l, int lda2, const __half* B2,
              __half* C2h, int N2, int K2, int ldc2, int bx_split)
{
    extern __shared__ char smraw[];
    const uint32_t sb = cvta_s(smraw);
    if ((int)blockIdx.x < bx_split)
        gemm_body<true>(sb, A1h, A1l, lda1, B1, nullptr, Q_hi, Q_lo, rope,
                        N1, K1, ldc1, blockIdx.y * 128, blockIdx.x * 128, 0);
    else
        gemm_body<false>(sb, A2h, A2l, lda2, B2, nullptr, C2h, nullptr, nullptr,
                         N2, K2, ldc2, blockIdx.y * 128,
                         (blockIdx.x - bx_split) * 128, 0);
}

// ---------------------------------------------------------------------------
// Grouped fp32 -> fp16 conversion + rope table — identical to R14
// ---------------------------------------------------------------------------
union HV4 { __half h[4]; ushort4 u; };

#define NV4_X   (MROWS * EMB / 4)
#define NV4_QA  (QRANK * EMB / 4)
#define NV4_KVA (576 * EMB / 4)
#define NV4_QB  ((NHEAD * QK_D) * QRANK / 4)
#define NV4_KVB (3072 * KVRANK / 4)
#define NV4_OW  (EMB * (NHEAD * V_D) / 4)
#define C1_ (NV4_X)
#define C2_ (C1_ + NV4_QA)
#define C3_ (C2_ + NV4_KVA)
#define C4_ (C3_ + NV4_QB)
#define C5_ (C4_ + NV4_KVB)
#define C6_ (C5_ + NV4_OW)
#define C7_ (C6_ + SLEN * 32)
#define SPLIT_BLOCKS ((C7_ + 255) / 256)

__global__ void split_all(const float* __restrict__ x,  const float* __restrict__ qa,
                          const float* __restrict__ kva, const float* __restrict__ qb,
                          const float* __restrict__ kvb, const float* __restrict__ ow,
                          __half* __restrict__ xh,  __half* __restrict__ xl,
                          __half* __restrict__ qkh, __half* __restrict__ qbh,
                          __half* __restrict__ kvbh, __half* __restrict__ owh,
                          float2* __restrict__ rope)
{
    const int i = blockIdx.x * blockDim.x + threadIdx.x;
    if (i >= C7_) return;

    if (i >= C6_) {
        const int e = i - C6_;
        const int s = e >> 5, t = e & 31;
        const float theta = powf(10000.f, -((float)(2 * t)) / 64.f);
        float sn, cs;
        sincosf((float)s * theta, &sn, &cs);
        rope[e] = make_float2(cs, sn);
        return;
    }

    const float* src; __half* hi; int o; bool do_lo = false;
    if (i < C1_)      { src = x;   hi = xh;   o = i;       do_lo = true; }
    else if (i < C2_) { src = qa;  hi = qkh;  o = i - C1_; }
    else if (i < C3_) { src = kva; hi = qkh + (size_t)QRANK * EMB; o = i - C2_; }
    else if (i < C4_) { src = qb;  hi = qbh;  o = i - C3_; }
    else if (i < C5_) { src = kvb; hi = kvbh; o = i - C4_; }
    else              { src = ow;  hi = owh;  o = i - C5_; }

    const float4 v = ((const float4*)src)[o];
    const float vv[4] = { v.x, v.y, v.z, v.w };
    HV4 H;
    #pragma unroll
    for (int j = 0; j < 4; ++j) H.h[j] = __float2half_rn(vv[j]);
    ((ushort4*)hi)[o] = H.u;
    if (do_lo) {
        HV4 L;
        #pragma unroll
        for (int j = 0; j < 4; ++j)
            L.h[j] = __float2half_rn(vv[j] - __half2float(H.h[j]));
        ((ushort4*)xl)[o] = L.u;
    }
}

// ---------------------------------------------------------------------------
// Fused repack: K (fp16 copy + rope from XC) + V transpose — identical to R14
// ---------------------------------------------------------------------------
__global__ __launch_bounds__(1024)
void repack_all(const __half* __restrict__ KVBh, const float* __restrict__ XC,
                const float2* __restrict__ rope,
                __half* __restrict__ Kh, __half* __restrict__ Vh)
{
    __shared__ __half tile[64][136];
    const int bb = blockIdx.x;
    const int tid = threadIdx.x;

    if (bb < MROWS) {
        const int bs = bb;
        const int b  = bs >> 11;
        const int s  = bs & 2047;
        const int h  = tid >> 6;
        const int t  = tid & 63;
        const size_t dst = ((size_t)(b * NHEAD + h) * SLEN + s) * QK_D + 2 * t;

        if (t < 32) {
            *(uint32_t*)(Kh + dst) =
                *(const uint32_t*)(KVBh + (size_t)bs * 3072 + h * 192 + 2 * t);
        } else {
            const int tr = t - 32;
            const float2 cs = rope[s * 32 + tr];
            const float* kr = XC + (size_t)bs * NXC + 2048;
            const float2 p = *(const float2*)(kr + 2 * tr);
            const float v0 = p.x * cs.x - p.y * cs.y;
            const float v1 = p.y * cs.x + p.x * cs.y;
            *(uint32_t*)(Kh + dst) = pack_h2(v0, v1);
        }
    } else {
        const int idx = bb - MROWS;
        const int bh  = idx >> 5;
        const int s0  = (idx & 31) * 64;
        const int b   = bh >> 4;
        const int h   = bh & 15;

        {
            const int r = tid >> 4;
            const int c = (tid & 15) * 8;
            const uint4 v = *(const uint4*)(KVBh + (size_t)(b * SLEN + s0 + r) * 3072
                                            + h * 192 + 64 + c);
            *(uint4*)&tile[r][c] = v;
        }
        __syncthreads();

        const int d = tid >> 3;
        const int chunk = tid & 7;
        const size_t obase = ((size_t)bh * 128 + d) * SLEN + s0 + chunk * 8;
        #pragma unroll
        for (int j = 0; j < 8; j += 2) {
            const uint32_t w = (uint32_t)__half_as_ushort(tile[chunk * 8 + j][d])
                             | ((uint32_t)__half_as_ushort(tile[chunk * 8 + j + 1][d]) << 16);
            *(uint32_t*)(Vh + obase + j) = w;
        }
    }
}

// ---------------------------------------------------------------------------
// Flash attention — identical to R14
// ---------------------------------------------------------------------------
#define QLDE 136
#define VLDE 72
#define OFF_QH 0
#define OFF_QL 17408
#define OFF_STG 34816
#define STG_SZ 35840
#define SOFF_KH 0
#define SOFF_VH 17408
#define FLASH_SMEM (OFF_STG + 2 * STG_SZ)   // 106496

__device__ __forceinline__ void fa_load_kv(
    uint32_t base, const __half* Kh, const __half* Vh, int bh, int kt, int tid)
{
    const size_t gk = ((size_t)bh * SLEN + kt * 64) * QK_D;
    #pragma unroll
    for (int i = tid; i < 1024; i += 128) {
        const int r = i >> 4, c = (i & 15) * 8;
        cp16(base + SOFF_KH + (uint32_t)(r * QLDE + c) * 2,
             Kh + gk + (size_t)r * QK_D + c);
    }
    const size_t gv = (size_t)bh * V_D * SLEN + kt * 64;
    #pragma unroll
    for (int i = tid; i < 1024; i += 128) {
        const int r = i >> 3, c = (i & 7) * 8;
        cp16(base + SOFF_VH + (uint32_t)(r * VLDE + c) * 2,
             Vh + gv + (size_t)r * SLEN + c);
    }
}

__global__ __launch_bounds__(128, 2)
void flash_mma(const __half* __restrict__ Qh, const __half* __restrict__ Ql,
               const __half* __restrict__ Kh, const __half* __restrict__ Vh,
               __half* __restrict__ Ohi, __half* __restrict__ Olo)
{
    extern __shared__ char smraw[];
    const uint32_t sb0 = cvta_s(smraw);

    const int tid  = threadIdx.x;
    const int wid  = tid >> 5;
    const int lane = tid & 31;
    const int bh = blockIdx.y;
    const int b  = bh >> 4;
    const int h  = bh & 15;
    const int q0 = blockIdx.x * 64;
    const int r_base = wid * 16;

    const size_t gq = ((size_t)(b * SLEN + q0)) * (NHEAD * QK_D) + h * QK_D;
    #pragma unroll
    for (int i = tid; i < 1024; i += 128) {
        const int r = i >> 4, c = (i & 15) * 8;
        const uint32_t so = (uint32_t)(r * QLDE + c) * 2;
        cp16(sb0 + OFF_QH + so, Qh + gq + (size_t)r * (NHEAD * QK_D) + c);
        cp16(sb0 + OFF_QL + so, Ql + gq + (size_t)r * (NHEAD * QK_D) + c);
    }
    fa_load_kv(sb0 + OFF_STG, Kh, Vh, bh, 0, tid);
    cp_commit();
    asm volatile("cp.async.wait_group 0;" ::: "memory");
    __syncthreads();

    uint32_t qfh[8][4], qfl[8][4];
    {
        const int ar = lane & 15;
        const int ac = ((lane >> 4) & 1) * 8;
        #pragma unroll
        for (int kf = 0; kf < 8; ++kf) {
            const uint32_t off = (uint32_t)((r_base + ar) * QLDE + kf * 16 + ac) * 2;
            ldm_x4(qfh[kf], sb0 + OFF_QH + off);
            ldm_x4(qfl[kf], sb0 + OFF_QL + off);
        }
    }

    float Oa[16][4];
    #pragma unroll
    for (int i = 0; i < 16; ++i)
        #pragma unroll
        for (int j = 0; j < 4; ++j) Oa[i][j] = 0.f;
    float m0 = -INFINITY, m1 = -INFINITY, l0 = 0.f, l1 = 0.f;

    const int krow = lane & 7;
    const int kcol = ((lane >> 3) & 3) * 8;

    for (int kt = 0; kt < SLEN / 64; ++kt) {
        if (kt + 1 < SLEN / 64) {
            fa_load_kv(sb0 + OFF_STG + ((kt + 1) & 1) * STG_SZ, Kh, Vh, bh, kt + 1, tid);
            cp_commit();
            asm volatile("cp.async.wait_group 1;" ::: "memory");
        } else {
            asm volatile("cp.async.wait_group 0;" ::: "memory");
        }
        __syncthreads();

        const uint32_t sk = sb0 + OFF_STG + (kt & 1) * STG_SZ;

        float S[8][4];
        #pragma unroll
        for (int i = 0; i < 8; ++i)
            #pragma unroll
            for (int j = 0; j < 4; ++j) S[i][j] = 0.f;

        #pragma unroll
        for (int nb = 0; nb < 8; ++nb) {
            #pragma unroll
            for (int kfp = 0; kfp < 4; ++kfp) {
                const uint32_t ko = (uint32_t)((nb * 8 + krow) * QLDE
                                               + kfp * 32 + kcol) * 2;
                uint32_t kfh[4];
                ldm_x4(kfh, sk + SOFF_KH + ko);
                mma_f16(S[nb], qfh[2 * kfp],     kfh);
                mma_f16(S[nb], qfh[2 * kfp + 1], kfh + 2);
                mma_f16(S[nb], qfl[2 * kfp],     kfh);
                mma_f16(S[nb], qfl[2 * kfp + 1], kfh + 2);
            }
        }

        float mx0 = -INFINITY, mx1 = -INFINITY;
        #pragma unroll
        for (int nb = 0; nb < 8; ++nb) {
            mx0 = fmaxf(mx0, fmaxf(S[nb][0], S[nb][1]));
            mx1 = fmaxf(mx1, fmaxf(S[nb][2], S[nb][3]));
        }
        mx0 = fmaxf(mx0, __shfl_xor_sync(0xffffffffu, mx0, 1));
        mx0 = fmaxf(mx0, __shfl_xor_sync(0xffffffffu, mx0, 2));
        mx1 = fmaxf(mx1, __shfl_xor_sync(0xffffffffu, mx1, 1));
        mx1 = fmaxf(mx1, __shfl_xor_sync(0xffffffffu, mx1, 2));

        const float mn0 = fmaxf(m0, mx0);
        const float mn1 = fmaxf(m1, mx1);
        const float f0 = __expf(m0 - mn0);
        const float f1 = __expf(m1 - mn1);
        m0 = mn0; m1 = mn1;

        float rs0 = 0.f, rs1 = 0.f;
        #pragma unroll
        for (int nb = 0; nb < 8; ++nb) {
            S[nb][0] = __expf(S[nb][0] - mn0);
            S[nb][1] = __expf(S[nb][1] - mn0);
            S[nb][2] = __expf(S[nb][2] - mn1);
            S[nb][3] = __expf(S[nb][3] - mn1);
            rs0 += S[nb][0] + S[nb][1];
            rs1 += S[nb][2] + S[nb][3];
        }
        rs0 += __shfl_xor_sync(0xffffffffu, rs0, 1);
        rs0 += __shfl_xor_sync(0xffffffffu, rs0, 2);
        rs1 += __shfl_xor_sync(0xffffffffu, rs1, 1);
        rs1 += __shfl_xor_sync(0xffffffffu, rs1, 2);
        l0 = l0 * f0 + rs0;
        l1 = l1 * f1 + rs1;

        #pragma unroll
        for (int i = 0; i < 16; ++i) {
            Oa[i][0] *= f0; Oa[i][1] *= f0;
            Oa[i][2] *= f1; Oa[i][3] *= f1;
        }

        uint32_t ph[4][4], pl[4][4];
        #pragma unroll
        for (int kf2 = 0; kf2 < 4; ++kf2) {
            const float* s0p = S[2 * kf2];
            const float* s1p = S[2 * kf2 + 1];
            ph[kf2][0] = pack_h2(s0p[0], s0p[1]);
            ph[kf2][1] = pack_h2(s0p[2], s0p[3]);
            ph[kf2][2] = pack_h2(s1p[0], s1p[1]);
            ph[kf2][3] = pack_h2(s1p[2], s1p[3]);
            pl[kf2][0] = pack_h2(h_res(s0p[0]), h_res(s0p[1]));
            pl[kf2][1] = pack_h2(h_res(s0p[2]), h_res(s0p[3]));
            pl[kf2][2] = pack_h2(h_res(s1p[0]), h_res(s1p[1]));
            pl[kf2][3] = pack_h2(h_res(s1p[2]), h_res(s1p[3]));
        }

        #pragma unroll
        for (int nb2 = 0; nb2 < 16; ++nb2) {
            #pragma unroll
            for (int kfp2 = 0; kfp2 < 2; ++kfp2) {
                const uint32_t vo = (uint32_t)((nb2 * 8 + krow) * VLDE
                                               + kfp2 * 32 + kcol) * 2;
                uint32_t vfh[4];
                ldm_x4(vfh, sk + SOFF_VH + vo);
                mma_f16(Oa[nb2], ph[2 * kfp2],     vfh);
                mma_f16(Oa[nb2], ph[2 * kfp2 + 1], vfh + 2);
                mma_f16(Oa[nb2], pl[2 * kfp2],     vfh);
                mma_f16(Oa[nb2], pl[2 * kfp2 + 1], vfh + 2);
            }
        }
        __syncthreads();
    }

    const float inv0 = 1.f / l0;
    const float inv1 = 1.f / l1;
    const int er = lane >> 2;
    const int ec = (lane & 3) * 2;
    const size_t row0 = (size_t)(b * SLEN + q0 + r_base + er) * (NHEAD * V_D) + h * V_D;
    const size_t row1 = row0 + (size_t)8 * (NHEAD * V_D);
    #pragma unroll
    for (int nb2 = 0; nb2 < 16; ++nb2) {
        const int col = nb2 * 8 + ec;
        const float a0 = Oa[nb2][0] * inv0, a1 = Oa[nb2][1] * inv0;
        const float a2 = Oa[nb2][2] * inv1, a3 = Oa[nb2][3] * inv1;
        *(uint32_t*)(Ohi + row0 + col) = pack_h2(a0, a1);
        *(uint32_t*)(Olo + row0 + col) = pack_h2(h_res(a0), h_res(a1));
        *(uint32_t*)(Ohi + row1 + col) = pack_h2(a2, a3);
        *(uint32_t*)(Olo + row1 + col) = pack_h2(h_res(a2), h_res(a3));
    }
}

// ---------------------------------------------------------------------------
extern "C" void kernel_launch(void* const* d_in, const int* in_sizes, int n_in,
                              void* d_out, int out_size)
{
    const float* x    = (const float*)d_in[0];
    const float* q_a  = (const float*)d_in[1];
    const float* q_b  = (const float*)d_in[2];
    const float* kv_a = (const float*)d_in[3];
    const float* kv_b = (const float*)d_in[4];
    const float* o_w  = (const float*)d_in[5];
    float* out = (float*)d_out;

    float *XC;
    float2* rope;
    cudaGetSymbolAddress((void**)&XC,   g_XC);
    cudaGetSymbolAddress((void**)&rope, g_rope);

    __half *x_hi, *x_lo, *qk_h, *qb_h, *kvb_h, *ow_h, *XC_hi, *XC_lo, *KVBh;
    __half *Qb_hi, *Qb_lo, *Kb_h, *Vt_h, *O_hi, *O_lo;
    cudaGetSymbolAddress((void**)&x_hi,  g_x_hi);
    cudaGetSymbolAddress((void**)&x_lo,  g_x_lo);
    cudaGetSymbolAddress((void**)&qk_h,  g_qakva_h);
    cudaGetSymbolAddress((void**)&qb_h,  g_qb_h);
    cudaGetSymbolAddress((void**)&kvb_h, g_kvb_h);
    cudaGetSymbolAddress((void**)&ow_h,  g_ow_h);
    cudaGetSymbolAddress((void**)&XC_hi, g_XC_hi);
    cudaGetSymbolAddress((void**)&XC_lo, g_XC_lo);
    cudaGetSymbolAddress((void**)&KVBh,  g_KVBh);
    cudaGetSymbolAddress((void**)&Qb_hi, g_Qb_hi);
    cudaGetSymbolAddress((void**)&Qb_lo, g_Qb_lo);
    cudaGetSymbolAddress((void**)&Kb_h,  g_Kb_h);
    cudaGetSymbolAddress((void**)&Vt_h,  g_Vt_h);
    cudaGetSymbolAddress((void**)&O_hi,  g_O_hi);
    cudaGetSymbolAddress((void**)&O_lo,  g_O_lo);

    cudaFuncSetAttribute(gemm_one, cudaFuncAttributeMaxDynamicSharedMemorySize,
                         GEMM_SMEM);
    cudaFuncSetAttribute(gemm_two, cudaFuncAttributeMaxDynamicSharedMemorySize,
                         GEMM_SMEM);
    cudaFuncSetAttribute(flash_mma, cudaFuncAttributeMaxDynamicSharedMemorySize,
                         FLASH_SMEM);

    // 1) conversions + rope table (single launch)
    split_all<<<SPLIT_BLOCKS, 256>>>(x, q_a, kv_a, q_b, kv_b, o_w,
                                     x_hi, x_lo, qk_h, qb_h, kvb_h, ow_h, rope);

    // 2) merged x-GEMM: XC = x @ [q_a; kv_a]^T (fp32 only for k_rot cols >=2048)
    gemm_one<<<dim3(17, 32), 256, GEMM_SMEM>>>(x_hi, x_lo, EMB, qk_h,
                                               XC, XC_hi, XC_lo, NXC, EMB, NXC, 2048);

    // 3) grouped: Q-GEMM (rope epilogue -> Qb hi/lo)  +  KVB-GEMM (fp16)
    gemm_two<<<dim3(16 + 24, 32), 256, GEMM_SMEM>>>(
        XC_hi, XC_lo, NXC, qb_h, Qb_hi, Qb_lo, rope, 2048, QRANK, 2048,
        XC_hi + QRANK, XC_lo + QRANK, NXC, kvb_h, KVBh, 3072, KVRANK, 3072,
        16);

    // 4) fused repack (K + V transpose only)
    repack_all<<<MROWS + 1024, 1024>>>(KVBh, XC, rope, Kb_h, Vt_h);

    // 5) attention (Q read with stride 2048)
    flash_mma<<<dim3(SLEN / 64, BHN), 128, FLASH_SMEM>>>(
        Qb_hi, Qb_lo, Kb_h, Vt_h, O_hi, O_lo);

    // 6) out = O @ o_w^T
    gemm_one<<<dim3(16, 32), 256, GEMM_SMEM>>>(O_hi, O_lo, EMB, ow_h,
                                               out, nullptr, nullptr,
                                               EMB, NHEAD * V_D, EMB, 0);
}